// round 8
// baseline (speedup 1.0000x reference)
#include <cuda_runtime.h>

#define N_NODES 50000
#define N_EDGES 500000
#define HID 128
#define EDIM 32

// ---------------- scratch (device globals: no allocation allowed) ----------------
__device__ float g_sum [N_NODES * HID];   // scatter-sum of encoded edges
__device__ float g_cnt [N_NODES];         // per-node edge counts
__device__ float g_hnew[N_NODES * HID];   // GRU output

// ---------------- zero scratch ----------------
__global__ void zero_k() {
    int i = blockIdx.x * blockDim.x + threadIdx.x;
    if (i < N_NODES * HID) g_sum[i] = 0.0f;
    if (i < N_NODES)       g_cnt[i] = 0.0f;
}

// ---------------- packed fp32x2 helpers (sm_100a FFMA2) ----------------
__device__ __forceinline__ unsigned long long fma2(unsigned long long a,
                                                   unsigned long long b,
                                                   unsigned long long c) {
    unsigned long long d;
    asm("fma.rn.f32x2 %0, %1, %2, %3;" : "=l"(d) : "l"(a), "l"(b), "l"(c));
    return d;
}
__device__ __forceinline__ unsigned long long dup2(float x) {
    unsigned int xi = __float_as_uint(x);
    unsigned long long d;
    asm("mov.b64 %0, {%1, %1};" : "=l"(d) : "r"(xi));
    return d;
}
__device__ __forceinline__ void unpack2(unsigned long long v, float& lo, float& hi) {
    asm("mov.b64 {%0, %1}, %2;" : "=f"(lo), "=f"(hi) : "l"(v));
}

__device__ __forceinline__ float4 ldg4(const float* p) {
    return __ldg((const float4*)p);
}
__device__ __forceinline__ ulonglong2 ldg2x64(const float* p) {
    return __ldg((const ulonglong2*)p);
}

// vector reduction atomic: 4 floats, no return (RED.128)
__device__ __forceinline__ void red_add_v4(float* p, float4 v) {
    asm volatile("red.global.add.v4.f32 [%0], {%1, %2, %3, %4};"
                 :: "l"(p), "f"(v.x), "f"(v.y), "f"(v.z), "f"(v.w) : "memory");
}

// LayerNorm(128) + affine + ReLU; lane holds channels lane*4..lane*4+3.
__device__ __forceinline__ float4 ln_relu(float4 v, float4 g, float4 b) {
    float s = v.x + v.y + v.z + v.w;
    float q = v.x * v.x + v.y * v.y + v.z * v.z + v.w * v.w;
#pragma unroll
    for (int o = 16; o > 0; o >>= 1) {
        s += __shfl_xor_sync(0xffffffffu, s, o);
        q += __shfl_xor_sync(0xffffffffu, q, o);
    }
    float mu   = s * (1.0f / 128.0f);
    float var  = q * (1.0f / 128.0f) - mu * mu;
    float rstd = rsqrtf(var + 1e-5f);
    float4 r;
    r.x = fmaxf((v.x - mu) * rstd * g.x + b.x, 0.0f);
    r.y = fmaxf((v.y - mu) * rstd * g.y + b.y, 0.0f);
    r.z = fmaxf((v.z - mu) * rstd * g.z + b.z, 0.0f);
    r.w = fmaxf((v.w - mu) * rstd * g.w + b.w, 0.0f);
    return r;
}

// 4 k-rows x 4 output channels for one edge: activations packed in registers.
#define FMA2_STEP4(AccA, AccB, A4, W0, W1r, W2r, W3r)                  \
    {                                                                   \
        unsigned long long _a0 = dup2(A4.x), _a1 = dup2(A4.y);          \
        unsigned long long _a2 = dup2(A4.z), _a3 = dup2(A4.w);          \
        AccA = fma2(_a0, W0.x,  AccA); AccB = fma2(_a0, W0.y,  AccB);   \
        AccA = fma2(_a1, W1r.x, AccA); AccB = fma2(_a1, W1r.y, AccB);   \
        AccA = fma2(_a2, W2r.x, AccA); AccB = fma2(_a2, W2r.y, AccB);   \
        AccA = fma2(_a3, W3r.x, AccA); AccB = fma2(_a3, W3r.y, AccB);   \
    }

// ---------------- kernel 1: edge encoder (Lin-LN-ReLU x2) + scatter-add ----------
// block = 128 threads = 4 warps; 8 edges/warp; 32 edges/block.
__global__ void __launch_bounds__(128) enc_scatter_k(
    const float* __restrict__ ea, const int* __restrict__ eidx,
    const float* __restrict__ W1, const float* __restrict__ b1,
    const float* __restrict__ g1, const float* __restrict__ be1,
    const float* __restrict__ W2, const float* __restrict__ b2,
    const float* __restrict__ g2, const float* __restrict__ be2)
{
    __shared__ float sEA[32 * EDIM];        // 4 KB raw edge_attr tile
    __shared__ float sH1[4][8][HID];        // 16 KB post-LN hidden

    const int tid  = threadIdx.x;
    const int w    = tid >> 5;
    const int lane = tid & 31;
    const int ch   = lane * 4;
    const long base = (long)blockIdx.x * 32;

    // cooperative coalesced load of 32 edges x 32 attrs
    ((float4*)sEA)[tid]       = ((const float4*)(ea + base * EDIM))[tid];
    ((float4*)sEA)[tid + 128] = ((const float4*)(ea + base * EDIM))[tid + 128];
    __syncthreads();

    // ---- layer 1: [8 edges,32] @ W1[32,128] ----
    unsigned long long aA[8], aB[8];
#pragma unroll
    for (int e = 0; e < 8; ++e) { aA[e] = 0ull; aB[e] = 0ull; }

#pragma unroll 4
    for (int i4 = 0; i4 < EDIM / 4; ++i4) {
        const float* wp = W1 + (i4 * 4) * HID + ch;
        ulonglong2 w0  = ldg2x64(wp);
        ulonglong2 w1r = ldg2x64(wp + HID);
        ulonglong2 w2r = ldg2x64(wp + 2 * HID);
        ulonglong2 w3r = ldg2x64(wp + 3 * HID);
#pragma unroll
        for (int e = 0; e < 8; ++e) {
            float4 a = *(const float4*)(sEA + (w * 8 + e) * EDIM + i4 * 4);
            FMA2_STEP4(aA[e], aB[e], a, w0, w1r, w2r, w3r)
        }
    }

    float4 b1v  = ldg4(b1 + ch);
    float4 g1v  = ldg4(g1 + ch);
    float4 be1v = ldg4(be1 + ch);
#pragma unroll
    for (int e = 0; e < 8; ++e) {
        float4 v;
        unpack2(aA[e], v.x, v.y);
        unpack2(aB[e], v.z, v.w);
        v.x += b1v.x; v.y += b1v.y; v.z += b1v.z; v.w += b1v.w;
        *(float4*)&sH1[w][e][ch] = ln_relu(v, g1v, be1v);
    }
    __syncwarp();

    // ---- layer 2: [8 edges,128] @ W2[128,128] ----
    unsigned long long cA[8], cB[8];
#pragma unroll
    for (int e = 0; e < 8; ++e) { cA[e] = 0ull; cB[e] = 0ull; }

#pragma unroll 4
    for (int i4 = 0; i4 < HID / 4; ++i4) {
        const float* wp = W2 + (i4 * 4) * HID + ch;
        ulonglong2 w0  = ldg2x64(wp);
        ulonglong2 w1r = ldg2x64(wp + HID);
        ulonglong2 w2r = ldg2x64(wp + 2 * HID);
        ulonglong2 w3r = ldg2x64(wp + 3 * HID);
#pragma unroll
        for (int e = 0; e < 8; ++e) {
            float4 a = *(const float4*)&sH1[w][e][i4 * 4];
            FMA2_STEP4(cA[e], cB[e], a, w0, w1r, w2r, w3r)
        }
    }

    float4 b2v  = ldg4(b2 + ch);
    float4 g2v  = ldg4(g2 + ch);
    float4 be2v = ldg4(be2 + ch);
#pragma unroll
    for (int e = 0; e < 8; ++e) {
        float4 v;
        unpack2(cA[e], v.x, v.y);
        unpack2(cB[e], v.z, v.w);
        v.x += b2v.x; v.y += b2v.y; v.z += b2v.z; v.w += b2v.w;
        float4 o = ln_relu(v, g2v, be2v);
        long eg = base + w * 8 + e;
        int  s  = eidx[eg];                 // src node
        red_add_v4(g_sum + (long)s * HID + ch, o);
        if (lane == 0) atomicAdd(&g_cnt[s], 1.0f);
    }
}

// ---------------- kernel 2: mean + GRUCell ----------------
// block = 384 threads (one per gate-row j of 3H), 8 nodes per block.
__global__ void __launch_bounds__(384) gru_k(
    const float* __restrict__ hprev,
    const float* __restrict__ Wih, const float* __restrict__ bih,
    const float* __restrict__ Whh, const float* __restrict__ bhh)
{
    __shared__ float sA[8][HID];
    __shared__ float sH[8][HID];
    __shared__ float sR[8][HID];
    __shared__ float sZ[8][HID];

    const int tid = threadIdx.x;
    const long node0 = (long)blockIdx.x * 8;

    for (int idx = tid; idx < 8 * HID; idx += 384) {
        int n = idx >> 7, k = idx & 127;
        long g = (node0 + n) * HID + k;
        float c = g_cnt[node0 + n];
        sA[n][k] = g_sum[g] / fmaxf(c, 1.0f);   // scatter-mean
        sH[n][k] = hprev[g];
    }
    __syncthreads();

    const int j = tid;                    // 0..383 : gate row (r|z|n)
    unsigned long long gx2[8], gh2[8];
#pragma unroll
    for (int n = 0; n < 8; ++n) { gx2[n] = 0ull; gh2[n] = 0ull; }

    const float* wi = Wih + (long)j * HID;
    const float* wh = Whh + (long)j * HID;
#pragma unroll 4
    for (int k4 = 0; k4 < HID / 4; ++k4) {
        ulonglong2 wi2 = ldg2x64(wi + k4 * 4);
        ulonglong2 wh2 = ldg2x64(wh + k4 * 4);
#pragma unroll
        for (int n = 0; n < 8; ++n) {
            ulonglong2 a2 = *(const ulonglong2*)&sA[n][k4 * 4];
            ulonglong2 h2 = *(const ulonglong2*)&sH[n][k4 * 4];
            gx2[n] = fma2(a2.x, wi2.x, gx2[n]);
            gx2[n] = fma2(a2.y, wi2.y, gx2[n]);
            gh2[n] = fma2(h2.x, wh2.x, gh2[n]);
            gh2[n] = fma2(h2.y, wh2.y, gh2[n]);
        }
    }

    float gx[8], gh[8];
    const float bi = __ldg(bih + j), bh = __ldg(bhh + j);
#pragma unroll
    for (int n = 0; n < 8; ++n) {
        float lo, hi;
        unpack2(gx2[n], lo, hi); gx[n] = bi + lo + hi;
        unpack2(gh2[n], lo, hi); gh[n] = bh + lo + hi;
    }

    if (j < HID) {
#pragma unroll
        for (int n = 0; n < 8; ++n)
            sR[n][j] = 1.0f / (1.0f + expf(-(gx[n] + gh[n])));
    } else if (j < 2 * HID) {
        int jj = j - HID;
#pragma unroll
        for (int n = 0; n < 8; ++n)
            sZ[n][jj] = 1.0f / (1.0f + expf(-(gx[n] + gh[n])));
    }
    __syncthreads();
    if (j >= 2 * HID) {
        int jj = j - 2 * HID;
#pragma unroll
        for (int n = 0; n < 8; ++n) {
            float r  = sR[n][jj];
            float nn = tanhf(gx[n] + r * gh[n]);
            float z  = sZ[n][jj];
            g_hnew[(node0 + n) * HID + jj] = (1.0f - z) * nn + z * sH[n][jj];
        }
    }
}

// ---------------- kernel 3: gather + concat + classifier ----------------
// block = 128 threads = 4 warps; 8 edges/warp; 32 edges/block.
__global__ void __launch_bounds__(128) cls_k(
    const float* __restrict__ ea, const int* __restrict__ eidx,
    const float* __restrict__ Wc1, const float* __restrict__ bc1,
    const float* __restrict__ Wc2, const float* __restrict__ bc2,
    float* __restrict__ out)
{
    __shared__ float sRep[4][8][2 * HID + EDIM];   // 288 floats/edge, 36.9 KB

    const int tid  = threadIdx.x;
    const int w    = tid >> 5;
    const int lane = tid & 31;
    const int ch   = lane * 4;
    const long base = (long)blockIdx.x * 32;

#pragma unroll
    for (int e = 0; e < 8; ++e) {
        long eg = base + w * 8 + e;
        int  s  = eidx[eg];
        int  d  = eidx[N_EDGES + eg];
        *(float4*)&sRep[w][e][ch]       = *(const float4*)(g_hnew + (long)s * HID + ch);
        *(float4*)&sRep[w][e][HID + ch] = *(const float4*)(g_hnew + (long)d * HID + ch);
        if (lane < 8)
            *(float4*)&sRep[w][e][2 * HID + lane * 4] =
                *(const float4*)(ea + eg * EDIM + lane * 4);
    }
    __syncwarp();

    unsigned long long aA[8], aB[8];
#pragma unroll
    for (int e = 0; e < 8; ++e) { aA[e] = 0ull; aB[e] = 0ull; }

#pragma unroll 4
    for (int i4 = 0; i4 < (2 * HID + EDIM) / 4; ++i4) {   // 72 iters
        const float* wp = Wc1 + (i4 * 4) * HID + ch;
        ulonglong2 w0  = ldg2x64(wp);
        ulonglong2 w1r = ldg2x64(wp + HID);
        ulonglong2 w2r = ldg2x64(wp + 2 * HID);
        ulonglong2 w3r = ldg2x64(wp + 3 * HID);
#pragma unroll
        for (int e = 0; e < 8; ++e) {
            float4 a = *(const float4*)&sRep[w][e][i4 * 4];
            FMA2_STEP4(aA[e], aB[e], a, w0, w1r, w2r, w3r)
        }
    }

    float4 bc1v = ldg4(bc1 + ch);
    float4 wc2v = ldg4(Wc2 + ch);
    const float bb = __ldg(bc2);
#pragma unroll
    for (int e = 0; e < 8; ++e) {
        float c0, c1, c2, c3;
        unpack2(aA[e], c0, c1);
        unpack2(aB[e], c2, c3);
        float t0 = fmaxf(c0 + bc1v.x, 0.0f);
        float t1 = fmaxf(c1 + bc1v.y, 0.0f);
        float t2 = fmaxf(c2 + bc1v.z, 0.0f);
        float t3 = fmaxf(c3 + bc1v.w, 0.0f);
        float p = t0 * wc2v.x + t1 * wc2v.y + t2 * wc2v.z + t3 * wc2v.w;
#pragma unroll
        for (int o = 16; o > 0; o >>= 1) p += __shfl_xor_sync(0xffffffffu, p, o);
        if (lane == 0) out[base + w * 8 + e] = p + bb;
    }
}

// ---------------- launch ----------------
extern "C" void kernel_launch(void* const* d_in, const int* in_sizes, int n_in,
                              void* d_out, int out_size)
{
    (void)in_sizes; (void)n_in; (void)out_size;

    // Maximize smem carveout so more 37KB-blocks become resident (occupancy).
    static int attr_done = 0;
    if (!attr_done) {
        cudaFuncSetAttribute(cls_k, cudaFuncAttributePreferredSharedMemoryCarveout, 100);
        cudaFuncSetAttribute(enc_scatter_k, cudaFuncAttributePreferredSharedMemoryCarveout, 100);
        cudaFuncSetAttribute(gru_k, cudaFuncAttributePreferredSharedMemoryCarveout, 100);
        attr_done = 1;
    }

    // 0:x 1:edge_index 2:edge_attr 3:h_prev 4:W1 5:b1 6:g1 7:be1
    // 8:W2 9:b2 10:g2 11:be2 12:Wih 13:bih 14:Whh 15:bhh 16:Wc1 17:bc1 18:Wc2 19:bc2
    const int*   eidx  = (const int*)  d_in[1];
    const float* ea    = (const float*)d_in[2];
    const float* hprev = (const float*)d_in[3];
    const float* W1 = (const float*)d_in[4];
    const float* b1 = (const float*)d_in[5];
    const float* g1 = (const float*)d_in[6];
    const float* be1= (const float*)d_in[7];
    const float* W2 = (const float*)d_in[8];
    const float* b2 = (const float*)d_in[9];
    const float* g2 = (const float*)d_in[10];
    const float* be2= (const float*)d_in[11];
    const float* Wih= (const float*)d_in[12];
    const float* bih= (const float*)d_in[13];
    const float* Whh= (const float*)d_in[14];
    const float* bhh= (const float*)d_in[15];
    const float* Wc1= (const float*)d_in[16];
    const float* bc1= (const float*)d_in[17];
    const float* Wc2= (const float*)d_in[18];
    const float* bc2= (const float*)d_in[19];
    float* out = (float*)d_out;

    zero_k<<<(N_NODES * HID + 255) / 256, 256>>>();
    enc_scatter_k<<<N_EDGES / 32, 128>>>(ea, eidx, W1, b1, g1, be1, W2, b2, g2, be2);
    gru_k<<<N_NODES / 8, 384>>>(hprev, Wih, bih, Whh, bhh);
    cls_k<<<N_EDGES / 32, 128>>>(ea, eidx, Wc1, bc1, Wc2, bc2, out);
}

// round 9
// speedup vs baseline: 1.1427x; 1.1427x over previous
#include <cuda_runtime.h>

#define N_NODES 50000
#define N_EDGES 500000
#define HID 128
#define EDIM 32
#define KTOT (2 * HID + EDIM)   // 288
#define RPAD 292                // padded smem row stride (292 % 32 = 4 -> no bank conflicts)
#define NKS (KTOT / 8)          // 36 k-steps

// ---------------- scratch (device globals: no allocation allowed) ----------------
__device__ float    g_sum [N_NODES * HID];
__device__ float    g_cnt [N_NODES];
__device__ float    g_hnew[N_NODES * HID];
__device__ unsigned g_wtf [KTOT * HID];     // Wc1 pre-converted to tf32 bit patterns

// ---------------- zero scratch ----------------
__global__ void zero_k() {
    int i = blockIdx.x * blockDim.x + threadIdx.x;
    if (i < N_NODES * HID) g_sum[i] = 0.0f;
    if (i < N_NODES)       g_cnt[i] = 0.0f;
}

// ---------------- tf32 helpers ----------------
__device__ __forceinline__ unsigned f2tf(float x) {
    unsigned r;
    asm("cvt.rna.tf32.f32 %0, %1;" : "=r"(r) : "f"(x));
    return r;
}
__device__ __forceinline__ float tf32f(float x) { return __uint_as_float(f2tf(x)); }

// pre-convert Wc1 to tf32
__global__ void prep_k(const float* __restrict__ Wc1) {
    int i = blockIdx.x * blockDim.x + threadIdx.x;
    if (i < KTOT * HID) g_wtf[i] = f2tf(Wc1[i]);
}

__device__ __forceinline__ void mma_tf32(float* d,
                                         unsigned a0, unsigned a1, unsigned a2, unsigned a3,
                                         unsigned b0, unsigned b1) {
    asm("mma.sync.aligned.m16n8k8.row.col.f32.tf32.tf32.f32 "
        "{%0,%1,%2,%3}, {%4,%5,%6,%7}, {%8,%9}, {%0,%1,%2,%3};"
        : "+f"(d[0]), "+f"(d[1]), "+f"(d[2]), "+f"(d[3])
        : "r"(a0), "r"(a1), "r"(a2), "r"(a3), "r"(b0), "r"(b1));
}

// ---------------- packed fp32x2 helpers (FFMA2) for encoder/GRU ----------------
__device__ __forceinline__ unsigned long long fma2(unsigned long long a,
                                                   unsigned long long b,
                                                   unsigned long long c) {
    unsigned long long d;
    asm("fma.rn.f32x2 %0, %1, %2, %3;" : "=l"(d) : "l"(a), "l"(b), "l"(c));
    return d;
}
__device__ __forceinline__ unsigned long long dup2(float x) {
    unsigned int xi = __float_as_uint(x);
    unsigned long long d;
    asm("mov.b64 %0, {%1, %1};" : "=l"(d) : "r"(xi));
    return d;
}
__device__ __forceinline__ void unpack2(unsigned long long v, float& lo, float& hi) {
    asm("mov.b64 {%0, %1}, %2;" : "=f"(lo), "=f"(hi) : "l"(v));
}
__device__ __forceinline__ float4 ldg4(const float* p) { return __ldg((const float4*)p); }
__device__ __forceinline__ ulonglong2 ldg2x64(const float* p) { return __ldg((const ulonglong2*)p); }

__device__ __forceinline__ float4 ln_relu(float4 v, float4 g, float4 b) {
    float s = v.x + v.y + v.z + v.w;
    float q = v.x * v.x + v.y * v.y + v.z * v.z + v.w * v.w;
#pragma unroll
    for (int o = 16; o > 0; o >>= 1) {
        s += __shfl_xor_sync(0xffffffffu, s, o);
        q += __shfl_xor_sync(0xffffffffu, q, o);
    }
    float mu   = s * (1.0f / 128.0f);
    float var  = q * (1.0f / 128.0f) - mu * mu;
    float rstd = rsqrtf(var + 1e-5f);
    float4 r;
    r.x = fmaxf((v.x - mu) * rstd * g.x + b.x, 0.0f);
    r.y = fmaxf((v.y - mu) * rstd * g.y + b.y, 0.0f);
    r.z = fmaxf((v.z - mu) * rstd * g.z + b.z, 0.0f);
    r.w = fmaxf((v.w - mu) * rstd * g.w + b.w, 0.0f);
    return r;
}

#define FMA2_STEP4(AccA, AccB, A4, W0, W1r, W2r, W3r)                  \
    {                                                                   \
        unsigned long long _a0 = dup2(A4.x), _a1 = dup2(A4.y);          \
        unsigned long long _a2 = dup2(A4.z), _a3 = dup2(A4.w);          \
        AccA = fma2(_a0, W0.x,  AccA); AccB = fma2(_a0, W0.y,  AccB);   \
        AccA = fma2(_a1, W1r.x, AccA); AccB = fma2(_a1, W1r.y, AccB);   \
        AccA = fma2(_a2, W2r.x, AccA); AccB = fma2(_a2, W2r.y, AccB);   \
        AccA = fma2(_a3, W3r.x, AccA); AccB = fma2(_a3, W3r.y, AccB);   \
    }

// ---------------- kernel 1: edge encoder + scatter-add (unchanged from R7) ----------
__global__ void __launch_bounds__(128) enc_scatter_k(
    const float* __restrict__ ea, const int* __restrict__ eidx,
    const float* __restrict__ W1, const float* __restrict__ b1,
    const float* __restrict__ g1, const float* __restrict__ be1,
    const float* __restrict__ W2, const float* __restrict__ b2,
    const float* __restrict__ g2, const float* __restrict__ be2)
{
    __shared__ float sEA[32 * EDIM];
    __shared__ float sH1[4][8][HID];

    const int tid  = threadIdx.x;
    const int w    = tid >> 5;
    const int lane = tid & 31;
    const int ch   = lane * 4;
    const long base = (long)blockIdx.x * 32;

    ((float4*)sEA)[tid]       = ((const float4*)(ea + base * EDIM))[tid];
    ((float4*)sEA)[tid + 128] = ((const float4*)(ea + base * EDIM))[tid + 128];
    __syncthreads();

    unsigned long long aA[8], aB[8];
#pragma unroll
    for (int e = 0; e < 8; ++e) { aA[e] = 0ull; aB[e] = 0ull; }

#pragma unroll 4
    for (int i4 = 0; i4 < EDIM / 4; ++i4) {
        const float* wp = W1 + (i4 * 4) * HID + ch;
        ulonglong2 w0  = ldg2x64(wp);
        ulonglong2 w1r = ldg2x64(wp + HID);
        ulonglong2 w2r = ldg2x64(wp + 2 * HID);
        ulonglong2 w3r = ldg2x64(wp + 3 * HID);
#pragma unroll
        for (int e = 0; e < 8; ++e) {
            float4 a = *(const float4*)(sEA + (w * 8 + e) * EDIM + i4 * 4);
            FMA2_STEP4(aA[e], aB[e], a, w0, w1r, w2r, w3r)
        }
    }

    float4 b1v  = ldg4(b1 + ch);
    float4 g1v  = ldg4(g1 + ch);
    float4 be1v = ldg4(be1 + ch);
#pragma unroll
    for (int e = 0; e < 8; ++e) {
        float4 v;
        unpack2(aA[e], v.x, v.y);
        unpack2(aB[e], v.z, v.w);
        v.x += b1v.x; v.y += b1v.y; v.z += b1v.z; v.w += b1v.w;
        *(float4*)&sH1[w][e][ch] = ln_relu(v, g1v, be1v);
    }
    __syncwarp();

    unsigned long long cA[8], cB[8];
#pragma unroll
    for (int e = 0; e < 8; ++e) { cA[e] = 0ull; cB[e] = 0ull; }

#pragma unroll 4
    for (int i4 = 0; i4 < HID / 4; ++i4) {
        const float* wp = W2 + (i4 * 4) * HID + ch;
        ulonglong2 w0  = ldg2x64(wp);
        ulonglong2 w1r = ldg2x64(wp + HID);
        ulonglong2 w2r = ldg2x64(wp + 2 * HID);
        ulonglong2 w3r = ldg2x64(wp + 3 * HID);
#pragma unroll
        for (int e = 0; e < 8; ++e) {
            float4 a = *(const float4*)&sH1[w][e][i4 * 4];
            FMA2_STEP4(cA[e], cB[e], a, w0, w1r, w2r, w3r)
        }
    }

    float4 b2v  = ldg4(b2 + ch);
    float4 g2v  = ldg4(g2 + ch);
    float4 be2v = ldg4(be2 + ch);
#pragma unroll
    for (int e = 0; e < 8; ++e) {
        float4 v;
        unpack2(cA[e], v.x, v.y);
        unpack2(cB[e], v.z, v.w);
        v.x += b2v.x; v.y += b2v.y; v.z += b2v.z; v.w += b2v.w;
        float4 o = ln_relu(v, g2v, be2v);
        long eg = base + w * 8 + e;
        int  s  = eidx[eg];
        float* dp = g_sum + (long)s * HID + ch;
        atomicAdd(dp + 0, o.x);
        atomicAdd(dp + 1, o.y);
        atomicAdd(dp + 2, o.z);
        atomicAdd(dp + 3, o.w);
        if (lane == 0) atomicAdd(&g_cnt[s], 1.0f);
    }
}

// ---------------- kernel 2: mean + GRUCell (unchanged from R7) ----------------
__global__ void __launch_bounds__(384) gru_k(
    const float* __restrict__ hprev,
    const float* __restrict__ Wih, const float* __restrict__ bih,
    const float* __restrict__ Whh, const float* __restrict__ bhh)
{
    __shared__ float sA[8][HID];
    __shared__ float sH[8][HID];
    __shared__ float sR[8][HID];
    __shared__ float sZ[8][HID];

    const int tid = threadIdx.x;
    const long node0 = (long)blockIdx.x * 8;

    for (int idx = tid; idx < 8 * HID; idx += 384) {
        int n = idx >> 7, k = idx & 127;
        long g = (node0 + n) * HID + k;
        float c = g_cnt[node0 + n];
        sA[n][k] = g_sum[g] / fmaxf(c, 1.0f);
        sH[n][k] = hprev[g];
    }
    __syncthreads();

    const int j = tid;
    unsigned long long gx2[8], gh2[8];
#pragma unroll
    for (int n = 0; n < 8; ++n) { gx2[n] = 0ull; gh2[n] = 0ull; }

    const float* wi = Wih + (long)j * HID;
    const float* wh = Whh + (long)j * HID;
#pragma unroll 4
    for (int k4 = 0; k4 < HID / 4; ++k4) {
        ulonglong2 wi2 = ldg2x64(wi + k4 * 4);
        ulonglong2 wh2 = ldg2x64(wh + k4 * 4);
#pragma unroll
        for (int n = 0; n < 8; ++n) {
            ulonglong2 a2 = *(const ulonglong2*)&sA[n][k4 * 4];
            ulonglong2 h2 = *(const ulonglong2*)&sH[n][k4 * 4];
            gx2[n] = fma2(a2.x, wi2.x, gx2[n]);
            gx2[n] = fma2(a2.y, wi2.y, gx2[n]);
            gh2[n] = fma2(h2.x, wh2.x, gh2[n]);
            gh2[n] = fma2(h2.y, wh2.y, gh2[n]);
        }
    }

    float gx[8], gh[8];
    const float bi = __ldg(bih + j), bh = __ldg(bhh + j);
#pragma unroll
    for (int n = 0; n < 8; ++n) {
        float lo, hi;
        unpack2(gx2[n], lo, hi); gx[n] = bi + lo + hi;
        unpack2(gh2[n], lo, hi); gh[n] = bh + lo + hi;
    }

    if (j < HID) {
#pragma unroll
        for (int n = 0; n < 8; ++n)
            sR[n][j] = 1.0f / (1.0f + expf(-(gx[n] + gh[n])));
    } else if (j < 2 * HID) {
        int jj = j - HID;
#pragma unroll
        for (int n = 0; n < 8; ++n)
            sZ[n][jj] = 1.0f / (1.0f + expf(-(gx[n] + gh[n])));
    }
    __syncthreads();
    if (j >= 2 * HID) {
        int jj = j - 2 * HID;
#pragma unroll
        for (int n = 0; n < 8; ++n) {
            float r  = sR[n][jj];
            float nn = tanhf(gx[n] + r * gh[n]);
            float z  = sZ[n][jj];
            g_hnew[(node0 + n) * HID + jj] = (1.0f - z) * nn + z * sH[n][jj];
        }
    }
}

// ---------------- kernel 3: classifier via tf32 mma.sync ----------------
// block = 128 threads = 4 warps; 64 edges/block staged in smem (tf32-rounded).
// Warp w computes output columns [w*32, w*32+32) for all 64 edges.
// D = rep[64,288] @ Wc1[288,128]; epilogue fuses bias+ReLU+Wc2 reduction.
__global__ void __launch_bounds__(128) cls_k(
    const float* __restrict__ ea, const int* __restrict__ eidx,
    const float* __restrict__ bc1, const float* __restrict__ Wc2,
    const float* __restrict__ bc2, float* __restrict__ out)
{
    extern __shared__ float sm[];
    float* srep = sm;               // 64 x RPAD
    float* part = sm + 64 * RPAD;   // 64 partial outputs

    const int tid  = threadIdx.x;
    const int w    = tid >> 5;
    const int lane = tid & 31;
    const int l4   = lane >> 2;     // groupID  (0..7)
    const int lm   = lane & 3;      // tig      (0..3)
    const long base = (long)blockIdx.x * 64;

    if (tid < 64) part[tid] = 0.0f;

    // gather + concat + tf32 rounding into smem (col = q*4 works for all ranges)
    for (int idx = tid; idx < 64 * 72; idx += 128) {
        int e = idx / 72, q = idx - e * 72;
        long eg = base + e;
        float4 v = make_float4(0.f, 0.f, 0.f, 0.f);
        if (eg < N_EDGES) {
            if (q < 32) {
                int s = eidx[eg];
                v = *(const float4*)(g_hnew + (long)s * HID + q * 4);
            } else if (q < 64) {
                int d = eidx[N_EDGES + eg];
                v = *(const float4*)(g_hnew + (long)d * HID + (q - 32) * 4);
            } else {
                v = *(const float4*)(ea + eg * EDIM + (q - 64) * 4);
            }
        }
        float4 t = make_float4(tf32f(v.x), tf32f(v.y), tf32f(v.z), tf32f(v.w));
        *(float4*)&srep[e * RPAD + q * 4] = t;
    }
    __syncthreads();

    float acc[4][4][4];
#pragma unroll
    for (int mt = 0; mt < 4; ++mt)
#pragma unroll
        for (int nt = 0; nt < 4; ++nt)
#pragma unroll
            for (int i = 0; i < 4; ++i) acc[mt][nt][i] = 0.0f;

    const int nw = w * 32;
#pragma unroll 4
    for (int ks = 0; ks < NKS; ++ks) {
        const int k0 = ks * 8;
        unsigned a[4][4];
#pragma unroll
        for (int mt = 0; mt < 4; ++mt) {
            const float* rp = srep + (mt * 16 + l4) * RPAD + k0 + lm;
            a[mt][0] = __float_as_uint(rp[0]);
            a[mt][1] = __float_as_uint(rp[8 * RPAD]);
            a[mt][2] = __float_as_uint(rp[4]);
            a[mt][3] = __float_as_uint(rp[8 * RPAD + 4]);
        }
#pragma unroll
        for (int nt = 0; nt < 4; ++nt) {
            int n = nw + nt * 8 + l4;
            unsigned b0 = __ldg(g_wtf + (k0 + lm) * HID + n);
            unsigned b1 = __ldg(g_wtf + (k0 + lm + 4) * HID + n);
#pragma unroll
            for (int mt = 0; mt < 4; ++mt)
                mma_tf32(acc[mt][nt], a[mt][0], a[mt][1], a[mt][2], a[mt][3], b0, b1);
        }
    }

    // epilogue: bias + ReLU + dot with Wc2, reduce quad (lm) via shfl, then smem atomics
#pragma unroll
    for (int nt = 0; nt < 4; ++nt) {
        int n0 = nw + nt * 8 + lm * 2;
        float bcA = __ldg(bc1 + n0),  bcB = __ldg(bc1 + n0 + 1);
        float w2A = __ldg(Wc2 + n0),  w2B = __ldg(Wc2 + n0 + 1);
#pragma unroll
        for (int mt = 0; mt < 4; ++mt) {
            float vlo = fmaxf(acc[mt][nt][0] + bcA, 0.f) * w2A
                      + fmaxf(acc[mt][nt][1] + bcB, 0.f) * w2B;
            float vhi = fmaxf(acc[mt][nt][2] + bcA, 0.f) * w2A
                      + fmaxf(acc[mt][nt][3] + bcB, 0.f) * w2B;
            vlo += __shfl_xor_sync(0xffffffffu, vlo, 1);
            vlo += __shfl_xor_sync(0xffffffffu, vlo, 2);
            vhi += __shfl_xor_sync(0xffffffffu, vhi, 1);
            vhi += __shfl_xor_sync(0xffffffffu, vhi, 2);
            if (lm == 0) {
                atomicAdd(&part[mt * 16 + l4],     vlo);
                atomicAdd(&part[mt * 16 + l4 + 8], vhi);
            }
        }
    }
    __syncthreads();

    if (tid < 64) {
        long eg = base + tid;
        if (eg < N_EDGES) out[eg] = part[tid] + __ldg(bc2);
    }
}

// ---------------- launch ----------------
extern "C" void kernel_launch(void* const* d_in, const int* in_sizes, int n_in,
                              void* d_out, int out_size)
{
    (void)in_sizes; (void)n_in; (void)out_size;
    const int*   eidx  = (const int*)  d_in[1];
    const float* ea    = (const float*)d_in[2];
    const float* hprev = (const float*)d_in[3];
    const float* W1 = (const float*)d_in[4];
    const float* b1 = (const float*)d_in[5];
    const float* g1 = (const float*)d_in[6];
    const float* be1= (const float*)d_in[7];
    const float* W2 = (const float*)d_in[8];
    const float* b2 = (const float*)d_in[9];
    const float* g2 = (const float*)d_in[10];
    const float* be2= (const float*)d_in[11];
    const float* Wih= (const float*)d_in[12];
    const float* bih= (const float*)d_in[13];
    const float* Whh= (const float*)d_in[14];
    const float* bhh= (const float*)d_in[15];
    const float* Wc1= (const float*)d_in[16];
    const float* bc1= (const float*)d_in[17];
    const float* Wc2= (const float*)d_in[18];
    const float* bc2= (const float*)d_in[19];
    float* out = (float*)d_out;

    const int cls_smem = (64 * RPAD + 64) * sizeof(float);   // 75008 B
    cudaFuncSetAttribute(cls_k, cudaFuncAttributeMaxDynamicSharedMemorySize, cls_smem);

    zero_k<<<(N_NODES * HID + 255) / 256, 256>>>();
    prep_k<<<(KTOT * HID + 255) / 256, 256>>>(Wc1);
    enc_scatter_k<<<N_EDGES / 32, 128>>>(ea, eidx, W1, b1, g1, be1, W2, b2, g2, be2);
    gru_k<<<N_NODES / 8, 384>>>(hprev, Wih, bih, Whh, bhh);
    cls_k<<<(N_EDGES + 63) / 64, 128, cls_smem>>>(ea, eidx, bc1, Wc2, bc2, out);
}

// round 10
// speedup vs baseline: 1.4967x; 1.3098x over previous
#include <cuda_runtime.h>

#define N_NODES 50000
#define N_EDGES 500000
#define HID 128
#define EDIM 32
#define KTOT (2 * HID + EDIM)   // 288
#define RPAD 292                // padded smem row stride (292 % 32 = 4 -> no bank conflicts)
#define NKS (KTOT / 8)          // 36 k-steps

typedef unsigned long long u64;

// ---------------- scratch (device globals: no allocation allowed) ----------------
__device__ float    g_sum [N_NODES * HID];
__device__ float    g_cnt [N_NODES];
__device__ float    g_hnew[N_NODES * HID];
__device__ unsigned g_wtf [KTOT * HID];       // Wc1 pre-converted to tf32
__device__ u64      g_wihT4[32 * 384 * 2];    // Wih transposed+interleaved (192 KB)
__device__ u64      g_whhT4[32 * 384 * 2];    // Whh transposed+interleaved (192 KB)

// ---------------- zero scratch ----------------
__global__ void zero_k() {
    int i = blockIdx.x * blockDim.x + threadIdx.x;
    if (i < N_NODES * HID) g_sum[i] = 0.0f;
    if (i < N_NODES)       g_cnt[i] = 0.0f;
}

// ---------------- tf32 helpers ----------------
__device__ __forceinline__ unsigned f2tf(float x) {
    unsigned r;
    asm("cvt.rna.tf32.f32 %0, %1;" : "=r"(r) : "f"(x));
    return r;
}
__device__ __forceinline__ float tf32f(float x) { return __uint_as_float(f2tf(x)); }

__global__ void prep_k(const float* __restrict__ Wc1) {
    int i = blockIdx.x * blockDim.x + threadIdx.x;
    if (i < KTOT * HID) g_wtf[i] = f2tf(Wc1[i]);
}

__device__ __forceinline__ u64 pk2(float lo, float hi) {
    return ((u64)__float_as_uint(hi) << 32) | (u64)__float_as_uint(lo);
}

// transpose+interleave GRU weights: entry [k4*384 + j] (as ulonglong2) holds
// {(w[j][4k4], w[j][4k4+1]), (w[j][4k4+2], w[j][4k4+3])}
__global__ void prep_gru_k(const float* __restrict__ Wih, const float* __restrict__ Whh) {
    int i = blockIdx.x * blockDim.x + threadIdx.x;   // over 32*384
    if (i < 32 * 384) {
        int k4 = i / 384, j = i - k4 * 384;
        const float* wi = Wih + (long)j * HID + k4 * 4;
        const float* wh = Whh + (long)j * HID + k4 * 4;
        g_wihT4[i * 2]     = pk2(wi[0], wi[1]);
        g_wihT4[i * 2 + 1] = pk2(wi[2], wi[3]);
        g_whhT4[i * 2]     = pk2(wh[0], wh[1]);
        g_whhT4[i * 2 + 1] = pk2(wh[2], wh[3]);
    }
}

__device__ __forceinline__ void mma_tf32(float* d,
                                         unsigned a0, unsigned a1, unsigned a2, unsigned a3,
                                         unsigned b0, unsigned b1) {
    asm("mma.sync.aligned.m16n8k8.row.col.f32.tf32.tf32.f32 "
        "{%0,%1,%2,%3}, {%4,%5,%6,%7}, {%8,%9}, {%0,%1,%2,%3};"
        : "+f"(d[0]), "+f"(d[1]), "+f"(d[2]), "+f"(d[3])
        : "r"(a0), "r"(a1), "r"(a2), "r"(a3), "r"(b0), "r"(b1));
}

// ---------------- packed fp32x2 helpers (FFMA2) ----------------
__device__ __forceinline__ u64 fma2(u64 a, u64 b, u64 c) {
    u64 d;
    asm("fma.rn.f32x2 %0, %1, %2, %3;" : "=l"(d) : "l"(a), "l"(b), "l"(c));
    return d;
}
__device__ __forceinline__ u64 dup2(float x) {
    unsigned int xi = __float_as_uint(x);
    u64 d;
    asm("mov.b64 %0, {%1, %1};" : "=l"(d) : "r"(xi));
    return d;
}
__device__ __forceinline__ void unpack2(u64 v, float& lo, float& hi) {
    asm("mov.b64 {%0, %1}, %2;" : "=f"(lo), "=f"(hi) : "l"(v));
}
__device__ __forceinline__ float4 ldg4(const float* p) { return __ldg((const float4*)p); }
__device__ __forceinline__ ulonglong2 ldg2x64(const float* p) { return __ldg((const ulonglong2*)p); }

__device__ __forceinline__ float4 ln_relu(float4 v, float4 g, float4 b) {
    float s = v.x + v.y + v.z + v.w;
    float q = v.x * v.x + v.y * v.y + v.z * v.z + v.w * v.w;
#pragma unroll
    for (int o = 16; o > 0; o >>= 1) {
        s += __shfl_xor_sync(0xffffffffu, s, o);
        q += __shfl_xor_sync(0xffffffffu, q, o);
    }
    float mu   = s * (1.0f / 128.0f);
    float var  = q * (1.0f / 128.0f) - mu * mu;
    float rstd = rsqrtf(var + 1e-5f);
    float4 r;
    r.x = fmaxf((v.x - mu) * rstd * g.x + b.x, 0.0f);
    r.y = fmaxf((v.y - mu) * rstd * g.y + b.y, 0.0f);
    r.z = fmaxf((v.z - mu) * rstd * g.z + b.z, 0.0f);
    r.w = fmaxf((v.w - mu) * rstd * g.w + b.w, 0.0f);
    return r;
}

#define FMA2_STEP4(AccA, AccB, A4, W0, W1r, W2r, W3r)                  \
    {                                                                   \
        u64 _a0 = dup2(A4.x), _a1 = dup2(A4.y);                         \
        u64 _a2 = dup2(A4.z), _a3 = dup2(A4.w);                         \
        AccA = fma2(_a0, W0.x,  AccA); AccB = fma2(_a0, W0.y,  AccB);   \
        AccA = fma2(_a1, W1r.x, AccA); AccB = fma2(_a1, W1r.y, AccB);   \
        AccA = fma2(_a2, W2r.x, AccA); AccB = fma2(_a2, W2r.y, AccB);   \
        AccA = fma2(_a3, W3r.x, AccA); AccB = fma2(_a3, W3r.y, AccB);   \
    }

// ---------------- kernel 1: edge encoder + scatter-add (unchanged) ----------
__global__ void __launch_bounds__(128) enc_scatter_k(
    const float* __restrict__ ea, const int* __restrict__ eidx,
    const float* __restrict__ W1, const float* __restrict__ b1,
    const float* __restrict__ g1, const float* __restrict__ be1,
    const float* __restrict__ W2, const float* __restrict__ b2,
    const float* __restrict__ g2, const float* __restrict__ be2)
{
    __shared__ float sEA[32 * EDIM];
    __shared__ float sH1[4][8][HID];

    const int tid  = threadIdx.x;
    const int w    = tid >> 5;
    const int lane = tid & 31;
    const int ch   = lane * 4;
    const long base = (long)blockIdx.x * 32;

    ((float4*)sEA)[tid]       = ((const float4*)(ea + base * EDIM))[tid];
    ((float4*)sEA)[tid + 128] = ((const float4*)(ea + base * EDIM))[tid + 128];
    __syncthreads();

    u64 aA[8], aB[8];
#pragma unroll
    for (int e = 0; e < 8; ++e) { aA[e] = 0ull; aB[e] = 0ull; }

#pragma unroll 4
    for (int i4 = 0; i4 < EDIM / 4; ++i4) {
        const float* wp = W1 + (i4 * 4) * HID + ch;
        ulonglong2 w0  = ldg2x64(wp);
        ulonglong2 w1r = ldg2x64(wp + HID);
        ulonglong2 w2r = ldg2x64(wp + 2 * HID);
        ulonglong2 w3r = ldg2x64(wp + 3 * HID);
#pragma unroll
        for (int e = 0; e < 8; ++e) {
            float4 a = *(const float4*)(sEA + (w * 8 + e) * EDIM + i4 * 4);
            FMA2_STEP4(aA[e], aB[e], a, w0, w1r, w2r, w3r)
        }
    }

    float4 b1v  = ldg4(b1 + ch);
    float4 g1v  = ldg4(g1 + ch);
    float4 be1v = ldg4(be1 + ch);
#pragma unroll
    for (int e = 0; e < 8; ++e) {
        float4 v;
        unpack2(aA[e], v.x, v.y);
        unpack2(aB[e], v.z, v.w);
        v.x += b1v.x; v.y += b1v.y; v.z += b1v.z; v.w += b1v.w;
        *(float4*)&sH1[w][e][ch] = ln_relu(v, g1v, be1v);
    }
    __syncwarp();

    u64 cA[8], cB[8];
#pragma unroll
    for (int e = 0; e < 8; ++e) { cA[e] = 0ull; cB[e] = 0ull; }

#pragma unroll 4
    for (int i4 = 0; i4 < HID / 4; ++i4) {
        const float* wp = W2 + (i4 * 4) * HID + ch;
        ulonglong2 w0  = ldg2x64(wp);
        ulonglong2 w1r = ldg2x64(wp + HID);
        ulonglong2 w2r = ldg2x64(wp + 2 * HID);
        ulonglong2 w3r = ldg2x64(wp + 3 * HID);
#pragma unroll
        for (int e = 0; e < 8; ++e) {
            float4 a = *(const float4*)&sH1[w][e][i4 * 4];
            FMA2_STEP4(cA[e], cB[e], a, w0, w1r, w2r, w3r)
        }
    }

    float4 b2v  = ldg4(b2 + ch);
    float4 g2v  = ldg4(g2 + ch);
    float4 be2v = ldg4(be2 + ch);
#pragma unroll
    for (int e = 0; e < 8; ++e) {
        float4 v;
        unpack2(cA[e], v.x, v.y);
        unpack2(cB[e], v.z, v.w);
        v.x += b2v.x; v.y += b2v.y; v.z += b2v.z; v.w += b2v.w;
        float4 o = ln_relu(v, g2v, be2v);
        long eg = base + w * 8 + e;
        int  s  = eidx[eg];
        float* dp = g_sum + (long)s * HID + ch;
        atomicAdd(dp + 0, o.x);
        atomicAdd(dp + 1, o.y);
        atomicAdd(dp + 2, o.z);
        atomicAdd(dp + 3, o.w);
        if (lane == 0) atomicAdd(&g_cnt[s], 1.0f);
    }
}

// ---------------- kernel 2: mean + GRUCell (coalesced transposed weights) ----------
// block = 384 threads (one per gate-row j), 8 nodes per block.
// Weight loads now lane-contiguous: LDG.128 = 4 lines instead of 32.
__global__ void __launch_bounds__(384) gru_k(
    const float* __restrict__ hprev,
    const float* __restrict__ bih, const float* __restrict__ bhh)
{
    __shared__ float sA[8][HID];
    __shared__ float sH[8][HID];
    __shared__ float sR[8][HID];
    __shared__ float sZ[8][HID];

    const int tid = threadIdx.x;
    const long node0 = (long)blockIdx.x * 8;

    for (int idx = tid; idx < 8 * HID; idx += 384) {
        int n = idx >> 7, k = idx & 127;
        long g = (node0 + n) * HID + k;
        float c = g_cnt[node0 + n];
        sA[n][k] = g_sum[g] / fmaxf(c, 1.0f);   // scatter-mean
        sH[n][k] = hprev[g];
    }
    __syncthreads();

    const int j = tid;                    // 0..383 : gate row (r|z|n)
    u64 gx2[8], gh2[8];
#pragma unroll
    for (int n = 0; n < 8; ++n) { gx2[n] = 0ull; gh2[n] = 0ull; }

    const ulonglong2* wiT = (const ulonglong2*)g_wihT4;
    const ulonglong2* whT = (const ulonglong2*)g_whhT4;
#pragma unroll 4
    for (int k4 = 0; k4 < HID / 4; ++k4) {
        ulonglong2 wi2 = __ldg(wiT + k4 * 384 + j);   // {(w4k,w4k+1),(w4k+2,w4k+3)}
        ulonglong2 wh2 = __ldg(whT + k4 * 384 + j);
#pragma unroll
        for (int n = 0; n < 8; ++n) {
            ulonglong2 a2 = *(const ulonglong2*)&sA[n][k4 * 4];
            ulonglong2 h2 = *(const ulonglong2*)&sH[n][k4 * 4];
            gx2[n] = fma2(a2.x, wi2.x, gx2[n]);
            gx2[n] = fma2(a2.y, wi2.y, gx2[n]);
            gh2[n] = fma2(h2.x, wh2.x, gh2[n]);
            gh2[n] = fma2(h2.y, wh2.y, gh2[n]);
        }
    }

    float gx[8], gh[8];
    const float bi = __ldg(bih + j), bh = __ldg(bhh + j);
#pragma unroll
    for (int n = 0; n < 8; ++n) {
        float lo, hi;
        unpack2(gx2[n], lo, hi); gx[n] = bi + lo + hi;
        unpack2(gh2[n], lo, hi); gh[n] = bh + lo + hi;
    }

    if (j < HID) {
#pragma unroll
        for (int n = 0; n < 8; ++n)
            sR[n][j] = 1.0f / (1.0f + expf(-(gx[n] + gh[n])));
    } else if (j < 2 * HID) {
        int jj = j - HID;
#pragma unroll
        for (int n = 0; n < 8; ++n)
            sZ[n][jj] = 1.0f / (1.0f + expf(-(gx[n] + gh[n])));
    }
    __syncthreads();
    if (j >= 2 * HID) {
        int jj = j - 2 * HID;
#pragma unroll
        for (int n = 0; n < 8; ++n) {
            float r  = sR[n][jj];
            float nn = tanhf(gx[n] + r * gh[n]);
            float z  = sZ[n][jj];
            g_hnew[(node0 + n) * HID + jj] = (1.0f - z) * nn + z * sH[n][jj];
        }
    }
}

// ---------------- kernel 3: classifier via tf32 mma.sync (unchanged) ----------------
__global__ void __launch_bounds__(128) cls_k(
    const float* __restrict__ ea, const int* __restrict__ eidx,
    const float* __restrict__ bc1, const float* __restrict__ Wc2,
    const float* __restrict__ bc2, float* __restrict__ out)
{
    extern __shared__ float sm[];
    float* srep = sm;               // 64 x RPAD
    float* part = sm + 64 * RPAD;   // 64 partial outputs

    const int tid  = threadIdx.x;
    const int w    = tid >> 5;
    const int lane = tid & 31;
    const int l4   = lane >> 2;
    const int lm   = lane & 3;
    const long base = (long)blockIdx.x * 64;

    if (tid < 64) part[tid] = 0.0f;

    for (int idx = tid; idx < 64 * 72; idx += 128) {
        int e = idx / 72, q = idx - e * 72;
        long eg = base + e;
        float4 v = make_float4(0.f, 0.f, 0.f, 0.f);
        if (eg < N_EDGES) {
            if (q < 32) {
                int s = eidx[eg];
                v = *(const float4*)(g_hnew + (long)s * HID + q * 4);
            } else if (q < 64) {
                int d = eidx[N_EDGES + eg];
                v = *(const float4*)(g_hnew + (long)d * HID + (q - 32) * 4);
            } else {
                v = *(const float4*)(ea + eg * EDIM + (q - 64) * 4);
            }
        }
        float4 t = make_float4(tf32f(v.x), tf32f(v.y), tf32f(v.z), tf32f(v.w));
        *(float4*)&srep[e * RPAD + q * 4] = t;
    }
    __syncthreads();

    float acc[4][4][4];
#pragma unroll
    for (int mt = 0; mt < 4; ++mt)
#pragma unroll
        for (int nt = 0; nt < 4; ++nt)
#pragma unroll
            for (int i = 0; i < 4; ++i) acc[mt][nt][i] = 0.0f;

    const int nw = w * 32;
#pragma unroll 4
    for (int ks = 0; ks < NKS; ++ks) {
        const int k0 = ks * 8;
        unsigned a[4][4];
#pragma unroll
        for (int mt = 0; mt < 4; ++mt) {
            const float* rp = srep + (mt * 16 + l4) * RPAD + k0 + lm;
            a[mt][0] = __float_as_uint(rp[0]);
            a[mt][1] = __float_as_uint(rp[8 * RPAD]);
            a[mt][2] = __float_as_uint(rp[4]);
            a[mt][3] = __float_as_uint(rp[8 * RPAD + 4]);
        }
#pragma unroll
        for (int nt = 0; nt < 4; ++nt) {
            int n = nw + nt * 8 + l4;
            unsigned b0 = __ldg(g_wtf + (k0 + lm) * HID + n);
            unsigned b1 = __ldg(g_wtf + (k0 + lm + 4) * HID + n);
#pragma unroll
            for (int mt = 0; mt < 4; ++mt)
                mma_tf32(acc[mt][nt], a[mt][0], a[mt][1], a[mt][2], a[mt][3], b0, b1);
        }
    }

#pragma unroll
    for (int nt = 0; nt < 4; ++nt) {
        int n0 = nw + nt * 8 + lm * 2;
        float bcA = __ldg(bc1 + n0),  bcB = __ldg(bc1 + n0 + 1);
        float w2A = __ldg(Wc2 + n0),  w2B = __ldg(Wc2 + n0 + 1);
#pragma unroll
        for (int mt = 0; mt < 4; ++mt) {
            float vlo = fmaxf(acc[mt][nt][0] + bcA, 0.f) * w2A
                      + fmaxf(acc[mt][nt][1] + bcB, 0.f) * w2B;
            float vhi = fmaxf(acc[mt][nt][2] + bcA, 0.f) * w2A
                      + fmaxf(acc[mt][nt][3] + bcB, 0.f) * w2B;
            vlo += __shfl_xor_sync(0xffffffffu, vlo, 1);
            vlo += __shfl_xor_sync(0xffffffffu, vlo, 2);
            vhi += __shfl_xor_sync(0xffffffffu, vhi, 1);
            vhi += __shfl_xor_sync(0xffffffffu, vhi, 2);
            if (lm == 0) {
                atomicAdd(&part[mt * 16 + l4],     vlo);
                atomicAdd(&part[mt * 16 + l4 + 8], vhi);
            }
        }
    }
    __syncthreads();

    if (tid < 64) {
        long eg = base + tid;
        if (eg < N_EDGES) out[eg] = part[tid] + __ldg(bc2);
    }
}

// ---------------- launch ----------------
extern "C" void kernel_launch(void* const* d_in, const int* in_sizes, int n_in,
                              void* d_out, int out_size)
{
    (void)in_sizes; (void)n_in; (void)out_size;
    const int*   eidx  = (const int*)  d_in[1];
    const float* ea    = (const float*)d_in[2];
    const float* hprev = (const float*)d_in[3];
    const float* W1 = (const float*)d_in[4];
    const float* b1 = (const float*)d_in[5];
    const float* g1 = (const float*)d_in[6];
    const float* be1= (const float*)d_in[7];
    const float* W2 = (const float*)d_in[8];
    const float* b2 = (const float*)d_in[9];
    const float* g2 = (const float*)d_in[10];
    const float* be2= (const float*)d_in[11];
    const float* Wih= (const float*)d_in[12];
    const float* bih= (const float*)d_in[13];
    const float* Whh= (const float*)d_in[14];
    const float* bhh= (const float*)d_in[15];
    const float* Wc1= (const float*)d_in[16];
    const float* bc1= (const float*)d_in[17];
    const float* Wc2= (const float*)d_in[18];
    const float* bc2= (const float*)d_in[19];
    float* out = (float*)d_out;

    const int cls_smem = (64 * RPAD + 64) * sizeof(float);   // 75008 B
    cudaFuncSetAttribute(cls_k, cudaFuncAttributeMaxDynamicSharedMemorySize, cls_smem);

    zero_k<<<(N_NODES * HID + 255) / 256, 256>>>();
    prep_k<<<(KTOT * HID + 255) / 256, 256>>>(Wc1);
    prep_gru_k<<<(32 * 384 + 255) / 256, 256>>>(Wih, Whh);
    enc_scatter_k<<<N_EDGES / 32, 128>>>(ea, eidx, W1, b1, g1, be1, W2, b2, g2, be2);
    gru_k<<<N_NODES / 8, 384>>>(hprev, bih, bhh);
    cls_k<<<(N_EDGES + 63) / 64, 128, cls_smem>>>(ea, eidx, bc1, Wc2, bc2, out);
}

// round 11
// speedup vs baseline: 1.6098x; 1.0756x over previous
#include <cuda_runtime.h>

#define N_NODES 50000
#define N_EDGES 500000
#define HID 128
#define EDIM 32
#define KTOT (2 * HID + EDIM)   // 288
#define RPAD 292                // cls smem row stride (292 % 32 = 4)
#define NKS (KTOT / 8)          // 36 k-steps for cls
#define S1STR 36                // enc layer1 A stride (36 % 32 = 4)
#define S2STR 132               // enc 128-wide row stride (132 % 32 = 4)

typedef unsigned long long u64;

// ---------------- scratch (device globals: no allocation allowed) ----------------
__device__ float    g_sum [N_NODES * HID];
__device__ float    g_cnt [N_NODES];
__device__ float    g_hnew[N_NODES * HID];
__device__ unsigned g_wtf [KTOT * HID];       // Wc1 tf32
__device__ unsigned g_w1tf[EDIM * HID];       // W1  tf32
__device__ unsigned g_w2tf[HID * HID];        // W2  tf32
__device__ u64      g_wihT4[32 * 384 * 2];    // Wih transposed+interleaved
__device__ u64      g_whhT4[32 * 384 * 2];    // Whh transposed+interleaved

// ---------------- zero scratch ----------------
__global__ void zero_k() {
    int i = blockIdx.x * blockDim.x + threadIdx.x;
    if (i < N_NODES * HID) g_sum[i] = 0.0f;
    if (i < N_NODES)       g_cnt[i] = 0.0f;
}

// ---------------- tf32 helpers ----------------
__device__ __forceinline__ unsigned f2tf(float x) {
    unsigned r;
    asm("cvt.rna.tf32.f32 %0, %1;" : "=r"(r) : "f"(x));
    return r;
}
__device__ __forceinline__ float tf32f(float x) { return __uint_as_float(f2tf(x)); }

__global__ void prep_all_k(const float* __restrict__ Wc1,
                           const float* __restrict__ W1,
                           const float* __restrict__ W2) {
    int i = blockIdx.x * blockDim.x + threadIdx.x;
    if (i < KTOT * HID) g_wtf [i] = f2tf(Wc1[i]);
    if (i < EDIM * HID) g_w1tf[i] = f2tf(W1[i]);
    if (i < HID  * HID) g_w2tf[i] = f2tf(W2[i]);
}

__device__ __forceinline__ u64 pk2(float lo, float hi) {
    return ((u64)__float_as_uint(hi) << 32) | (u64)__float_as_uint(lo);
}

__global__ void prep_gru_k(const float* __restrict__ Wih, const float* __restrict__ Whh) {
    int i = blockIdx.x * blockDim.x + threadIdx.x;   // over 32*384
    if (i < 32 * 384) {
        int k4 = i / 384, j = i - k4 * 384;
        const float* wi = Wih + (long)j * HID + k4 * 4;
        const float* wh = Whh + (long)j * HID + k4 * 4;
        g_wihT4[i * 2]     = pk2(wi[0], wi[1]);
        g_wihT4[i * 2 + 1] = pk2(wi[2], wi[3]);
        g_whhT4[i * 2]     = pk2(wh[0], wh[1]);
        g_whhT4[i * 2 + 1] = pk2(wh[2], wh[3]);
    }
}

__device__ __forceinline__ void mma_tf32(float* d,
                                         unsigned a0, unsigned a1, unsigned a2, unsigned a3,
                                         unsigned b0, unsigned b1) {
    asm("mma.sync.aligned.m16n8k8.row.col.f32.tf32.tf32.f32 "
        "{%0,%1,%2,%3}, {%4,%5,%6,%7}, {%8,%9}, {%0,%1,%2,%3};"
        : "+f"(d[0]), "+f"(d[1]), "+f"(d[2]), "+f"(d[3])
        : "r"(a0), "r"(a1), "r"(a2), "r"(a3), "r"(b0), "r"(b1));
}

// ---------------- packed fp32x2 helpers (FFMA2, used by gru) ----------------
__device__ __forceinline__ u64 fma2(u64 a, u64 b, u64 c) {
    u64 d;
    asm("fma.rn.f32x2 %0, %1, %2, %3;" : "=l"(d) : "l"(a), "l"(b), "l"(c));
    return d;
}
__device__ __forceinline__ void unpack2(u64 v, float& lo, float& hi) {
    asm("mov.b64 {%0, %1}, %2;" : "=f"(lo), "=f"(hi) : "l"(v));
}
__device__ __forceinline__ float4 ldg4(const float* p) { return __ldg((const float4*)p); }

__device__ __forceinline__ float4 ln_relu(float4 v, float4 g, float4 b) {
    float s = v.x + v.y + v.z + v.w;
    float q = v.x * v.x + v.y * v.y + v.z * v.z + v.w * v.w;
#pragma unroll
    for (int o = 16; o > 0; o >>= 1) {
        s += __shfl_xor_sync(0xffffffffu, s, o);
        q += __shfl_xor_sync(0xffffffffu, q, o);
    }
    float mu   = s * (1.0f / 128.0f);
    float var  = q * (1.0f / 128.0f) - mu * mu;
    float rstd = rsqrtf(var + 1e-5f);
    float4 r;
    r.x = fmaxf((v.x - mu) * rstd * g.x + b.x, 0.0f);
    r.y = fmaxf((v.y - mu) * rstd * g.y + b.y, 0.0f);
    r.z = fmaxf((v.z - mu) * rstd * g.z + b.z, 0.0f);
    r.w = fmaxf((v.w - mu) * rstd * g.w + b.w, 0.0f);
    return r;
}

// ---------------- kernel 1: edge encoder via tf32 MMA + scatter-add ----------------
// block = 128 threads = 4 warps; 64 edges/block.
// L1: [64,32]@W1[32,128] -> LN/ReLU -> L2: [64,128]@W2[128,128] -> LN/ReLU -> atomics.
__global__ void __launch_bounds__(128) enc_mma_k(
    const float* __restrict__ ea, const int* __restrict__ eidx,
    const float* __restrict__ b1, const float* __restrict__ g1,
    const float* __restrict__ be1,
    const float* __restrict__ b2, const float* __restrict__ g2,
    const float* __restrict__ be2)
{
    extern __shared__ float sm[];
    float* s0 = sm;                 // A buffer (stride S1STR for L1, S2STR for L2)
    float* s1 = sm + 64 * S2STR;    // D scratch (stride S2STR)

    const int tid  = threadIdx.x;
    const int w    = tid >> 5;
    const int lane = tid & 31;
    const int l4   = lane >> 2;
    const int lm   = lane & 3;
    const int ch   = lane * 4;
    const long base = (long)blockIdx.x * 64;

    // ---- phase A: gather edge_attr -> s0 (tf32, stride 36) ----
    for (int idx = tid; idx < 64 * 8; idx += 128) {
        int e = idx >> 3, q = idx & 7;
        long eg = base + e;
        float4 v = make_float4(0.f, 0.f, 0.f, 0.f);
        if (eg < N_EDGES) v = ldg4(ea + eg * EDIM + q * 4);
        float4 t = make_float4(tf32f(v.x), tf32f(v.y), tf32f(v.z), tf32f(v.w));
        *(float4*)&s0[e * S1STR + q * 4] = t;
    }
    __syncthreads();

    float acc[4][4][4];
    const int nw = w * 32;

    // ---- phase B: layer 1 MMA (K=32, 4 k-steps) ----
#pragma unroll
    for (int mt = 0; mt < 4; ++mt)
#pragma unroll
        for (int nt = 0; nt < 4; ++nt)
#pragma unroll
            for (int i = 0; i < 4; ++i) acc[mt][nt][i] = 0.0f;

#pragma unroll
    for (int ks = 0; ks < 4; ++ks) {
        const int k0 = ks * 8;
        unsigned a[4][4];
#pragma unroll
        for (int mt = 0; mt < 4; ++mt) {
            const float* rp = s0 + (mt * 16 + l4) * S1STR + k0 + lm;
            a[mt][0] = __float_as_uint(rp[0]);
            a[mt][1] = __float_as_uint(rp[8 * S1STR]);
            a[mt][2] = __float_as_uint(rp[4]);
            a[mt][3] = __float_as_uint(rp[8 * S1STR + 4]);
        }
#pragma unroll
        for (int nt = 0; nt < 4; ++nt) {
            int n = nw + nt * 8 + l4;
            unsigned b0 = __ldg(g_w1tf + (k0 + lm) * HID + n);
            unsigned b1f = __ldg(g_w1tf + (k0 + lm + 4) * HID + n);
#pragma unroll
            for (int mt = 0; mt < 4; ++mt)
                mma_tf32(acc[mt][nt], a[mt][0], a[mt][1], a[mt][2], a[mt][3], b0, b1f);
        }
    }
    __syncthreads();   // all reads of s0 done before D-store (s1) + later s0 reuse

    // store D1 -> s1
#pragma unroll
    for (int mt = 0; mt < 4; ++mt)
#pragma unroll
        for (int nt = 0; nt < 4; ++nt) {
            int row = mt * 16 + l4;
            int col = nw + nt * 8 + lm * 2;
            s1[row * S2STR + col]           = acc[mt][nt][0];
            s1[row * S2STR + col + 1]       = acc[mt][nt][1];
            s1[(row + 8) * S2STR + col]     = acc[mt][nt][2];
            s1[(row + 8) * S2STR + col + 1] = acc[mt][nt][3];
        }
    __syncthreads();

    // ---- phase C: bias + LN + ReLU -> s0 (tf32, stride 132) ----
    {
        float4 b1v  = ldg4(b1 + ch);
        float4 g1v  = ldg4(g1 + ch);
        float4 be1v = ldg4(be1 + ch);
        for (int r = 0; r < 16; ++r) {
            int row = w * 16 + r;
            float4 v = *(float4*)&s1[row * S2STR + ch];
            v.x += b1v.x; v.y += b1v.y; v.z += b1v.z; v.w += b1v.w;
            float4 o = ln_relu(v, g1v, be1v);
            float4 t = make_float4(tf32f(o.x), tf32f(o.y), tf32f(o.z), tf32f(o.w));
            *(float4*)&s0[row * S2STR + ch] = t;
        }
    }
    __syncthreads();

    // ---- phase D: layer 2 MMA (K=128, 16 k-steps) ----
#pragma unroll
    for (int mt = 0; mt < 4; ++mt)
#pragma unroll
        for (int nt = 0; nt < 4; ++nt)
#pragma unroll
            for (int i = 0; i < 4; ++i) acc[mt][nt][i] = 0.0f;

#pragma unroll 4
    for (int ks = 0; ks < 16; ++ks) {
        const int k0 = ks * 8;
        unsigned a[4][4];
#pragma unroll
        for (int mt = 0; mt < 4; ++mt) {
            const float* rp = s0 + (mt * 16 + l4) * S2STR + k0 + lm;
            a[mt][0] = __float_as_uint(rp[0]);
            a[mt][1] = __float_as_uint(rp[8 * S2STR]);
            a[mt][2] = __float_as_uint(rp[4]);
            a[mt][3] = __float_as_uint(rp[8 * S2STR + 4]);
        }
#pragma unroll
        for (int nt = 0; nt < 4; ++nt) {
            int n = nw + nt * 8 + l4;
            unsigned b0 = __ldg(g_w2tf + (k0 + lm) * HID + n);
            unsigned b1f = __ldg(g_w2tf + (k0 + lm + 4) * HID + n);
#pragma unroll
            for (int mt = 0; mt < 4; ++mt)
                mma_tf32(acc[mt][nt], a[mt][0], a[mt][1], a[mt][2], a[mt][3], b0, b1f);
        }
    }
    __syncthreads();

    // store D2 -> s1
#pragma unroll
    for (int mt = 0; mt < 4; ++mt)
#pragma unroll
        for (int nt = 0; nt < 4; ++nt) {
            int row = mt * 16 + l4;
            int col = nw + nt * 8 + lm * 2;
            s1[row * S2STR + col]           = acc[mt][nt][0];
            s1[row * S2STR + col + 1]       = acc[mt][nt][1];
            s1[(row + 8) * S2STR + col]     = acc[mt][nt][2];
            s1[(row + 8) * S2STR + col + 1] = acc[mt][nt][3];
        }
    __syncthreads();

    // ---- phase E: bias + LN + ReLU + scatter-add ----
    {
        float4 b2v  = ldg4(b2 + ch);
        float4 g2v  = ldg4(g2 + ch);
        float4 be2v = ldg4(be2 + ch);
        for (int r = 0; r < 16; ++r) {
            int row = w * 16 + r;
            long eg = base + row;
            float4 v = *(float4*)&s1[row * S2STR + ch];
            v.x += b2v.x; v.y += b2v.y; v.z += b2v.z; v.w += b2v.w;
            float4 o = ln_relu(v, g2v, be2v);
            if (eg < N_EDGES) {
                int s = eidx[eg];
                float* dp = g_sum + (long)s * HID + ch;
                atomicAdd(dp + 0, o.x);
                atomicAdd(dp + 1, o.y);
                atomicAdd(dp + 2, o.z);
                atomicAdd(dp + 3, o.w);
                if (lane == 0) atomicAdd(&g_cnt[s], 1.0f);
            }
        }
    }
}

// ---------------- kernel 2: mean + GRUCell (coalesced transposed weights) ----------
__global__ void __launch_bounds__(384) gru_k(
    const float* __restrict__ hprev,
    const float* __restrict__ bih, const float* __restrict__ bhh)
{
    __shared__ float sA[8][HID];
    __shared__ float sH[8][HID];
    __shared__ float sR[8][HID];
    __shared__ float sZ[8][HID];

    const int tid = threadIdx.x;
    const long node0 = (long)blockIdx.x * 8;

    for (int idx = tid; idx < 8 * HID; idx += 384) {
        int n = idx >> 7, k = idx & 127;
        long g = (node0 + n) * HID + k;
        float c = g_cnt[node0 + n];
        sA[n][k] = g_sum[g] / fmaxf(c, 1.0f);
        sH[n][k] = hprev[g];
    }
    __syncthreads();

    const int j = tid;
    u64 gx2[8], gh2[8];
#pragma unroll
    for (int n = 0; n < 8; ++n) { gx2[n] = 0ull; gh2[n] = 0ull; }

    const ulonglong2* wiT = (const ulonglong2*)g_wihT4;
    const ulonglong2* whT = (const ulonglong2*)g_whhT4;
#pragma unroll 4
    for (int k4 = 0; k4 < HID / 4; ++k4) {
        ulonglong2 wi2 = __ldg(wiT + k4 * 384 + j);
        ulonglong2 wh2 = __ldg(whT + k4 * 384 + j);
#pragma unroll
        for (int n = 0; n < 8; ++n) {
            ulonglong2 a2 = *(const ulonglong2*)&sA[n][k4 * 4];
            ulonglong2 h2 = *(const ulonglong2*)&sH[n][k4 * 4];
            gx2[n] = fma2(a2.x, wi2.x, gx2[n]);
            gx2[n] = fma2(a2.y, wi2.y, gx2[n]);
            gh2[n] = fma2(h2.x, wh2.x, gh2[n]);
            gh2[n] = fma2(h2.y, wh2.y, gh2[n]);
        }
    }

    float gx[8], gh[8];
    const float bi = __ldg(bih + j), bh = __ldg(bhh + j);
#pragma unroll
    for (int n = 0; n < 8; ++n) {
        float lo, hi;
        unpack2(gx2[n], lo, hi); gx[n] = bi + lo + hi;
        unpack2(gh2[n], lo, hi); gh[n] = bh + lo + hi;
    }

    if (j < HID) {
#pragma unroll
        for (int n = 0; n < 8; ++n)
            sR[n][j] = 1.0f / (1.0f + expf(-(gx[n] + gh[n])));
    } else if (j < 2 * HID) {
        int jj = j - HID;
#pragma unroll
        for (int n = 0; n < 8; ++n)
            sZ[n][jj] = 1.0f / (1.0f + expf(-(gx[n] + gh[n])));
    }
    __syncthreads();
    if (j >= 2 * HID) {
        int jj = j - 2 * HID;
#pragma unroll
        for (int n = 0; n < 8; ++n) {
            float r  = sR[n][jj];
            float nn = tanhf(gx[n] + r * gh[n]);
            float z  = sZ[n][jj];
            g_hnew[(node0 + n) * HID + jj] = (1.0f - z) * nn + z * sH[n][jj];
        }
    }
}

// ---------------- kernel 3: classifier via tf32 mma.sync ----------------
__global__ void __launch_bounds__(128) cls_k(
    const float* __restrict__ ea, const int* __restrict__ eidx,
    const float* __restrict__ bc1, const float* __restrict__ Wc2,
    const float* __restrict__ bc2, float* __restrict__ out)
{
    extern __shared__ float sm[];
    float* srep = sm;               // 64 x RPAD
    float* part = sm + 64 * RPAD;   // 64 partial outputs

    const int tid  = threadIdx.x;
    const int w    = tid >> 5;
    const int lane = tid & 31;
    const int l4   = lane >> 2;
    const int lm   = lane & 3;
    const long base = (long)blockIdx.x * 64;

    if (tid < 64) part[tid] = 0.0f;

    for (int idx = tid; idx < 64 * 72; idx += 128) {
        int e = idx / 72, q = idx - e * 72;
        long eg = base + e;
        float4 v = make_float4(0.f, 0.f, 0.f, 0.f);
        if (eg < N_EDGES) {
            if (q < 32) {
                int s = eidx[eg];
                v = *(const float4*)(g_hnew + (long)s * HID + q * 4);
            } else if (q < 64) {
                int d = eidx[N_EDGES + eg];
                v = *(const float4*)(g_hnew + (long)d * HID + (q - 32) * 4);
            } else {
                v = *(const float4*)(ea + eg * EDIM + (q - 64) * 4);
            }
        }
        float4 t = make_float4(tf32f(v.x), tf32f(v.y), tf32f(v.z), tf32f(v.w));
        *(float4*)&srep[e * RPAD + q * 4] = t;
    }
    __syncthreads();

    float acc[4][4][4];
#pragma unroll
    for (int mt = 0; mt < 4; ++mt)
#pragma unroll
        for (int nt = 0; nt < 4; ++nt)
#pragma unroll
            for (int i = 0; i < 4; ++i) acc[mt][nt][i] = 0.0f;

    const int nw = w * 32;
#pragma unroll 4
    for (int ks = 0; ks < NKS; ++ks) {
        const int k0 = ks * 8;
        unsigned a[4][4];
#pragma unroll
        for (int mt = 0; mt < 4; ++mt) {
            const float* rp = srep + (mt * 16 + l4) * RPAD + k0 + lm;
            a[mt][0] = __float_as_uint(rp[0]);
            a[mt][1] = __float_as_uint(rp[8 * RPAD]);
            a[mt][2] = __float_as_uint(rp[4]);
            a[mt][3] = __float_as_uint(rp[8 * RPAD + 4]);
        }
#pragma unroll
        for (int nt = 0; nt < 4; ++nt) {
            int n = nw + nt * 8 + l4;
            unsigned b0 = __ldg(g_wtf + (k0 + lm) * HID + n);
            unsigned b1 = __ldg(g_wtf + (k0 + lm + 4) * HID + n);
#pragma unroll
            for (int mt = 0; mt < 4; ++mt)
                mma_tf32(acc[mt][nt], a[mt][0], a[mt][1], a[mt][2], a[mt][3], b0, b1);
        }
    }

#pragma unroll
    for (int nt = 0; nt < 4; ++nt) {
        int n0 = nw + nt * 8 + lm * 2;
        float bcA = __ldg(bc1 + n0),  bcB = __ldg(bc1 + n0 + 1);
        float w2A = __ldg(Wc2 + n0),  w2B = __ldg(Wc2 + n0 + 1);
#pragma unroll
        for (int mt = 0; mt < 4; ++mt) {
            float vlo = fmaxf(acc[mt][nt][0] + bcA, 0.f) * w2A
                      + fmaxf(acc[mt][nt][1] + bcB, 0.f) * w2B;
            float vhi = fmaxf(acc[mt][nt][2] + bcA, 0.f) * w2A
                      + fmaxf(acc[mt][nt][3] + bcB, 0.f) * w2B;
            vlo += __shfl_xor_sync(0xffffffffu, vlo, 1);
            vlo += __shfl_xor_sync(0xffffffffu, vlo, 2);
            vhi += __shfl_xor_sync(0xffffffffu, vhi, 1);
            vhi += __shfl_xor_sync(0xffffffffu, vhi, 2);
            if (lm == 0) {
                atomicAdd(&part[mt * 16 + l4],     vlo);
                atomicAdd(&part[mt * 16 + l4 + 8], vhi);
            }
        }
    }
    __syncthreads();

    if (tid < 64) {
        long eg = base + tid;
        if (eg < N_EDGES) out[eg] = part[tid] + __ldg(bc2);
    }
}

// ---------------- launch ----------------
extern "C" void kernel_launch(void* const* d_in, const int* in_sizes, int n_in,
                              void* d_out, int out_size)
{
    (void)in_sizes; (void)n_in; (void)out_size;
    const int*   eidx  = (const int*)  d_in[1];
    const float* ea    = (const float*)d_in[2];
    const float* hprev = (const float*)d_in[3];
    const float* W1 = (const float*)d_in[4];
    const float* b1 = (const float*)d_in[5];
    const float* g1 = (const float*)d_in[6];
    const float* be1= (const float*)d_in[7];
    const float* W2 = (const float*)d_in[8];
    const float* b2 = (const float*)d_in[9];
    const float* g2 = (const float*)d_in[10];
    const float* be2= (const float*)d_in[11];
    const float* Wih= (const float*)d_in[12];
    const float* bih= (const float*)d_in[13];
    const float* Whh= (const float*)d_in[14];
    const float* bhh= (const float*)d_in[15];
    const float* Wc1= (const float*)d_in[16];
    const float* bc1= (const float*)d_in[17];
    const float* Wc2= (const float*)d_in[18];
    const float* bc2= (const float*)d_in[19];
    float* out = (float*)d_out;

    const int cls_smem = (64 * RPAD + 64) * sizeof(float);   // 75008 B
    const int enc_smem = (2 * 64 * S2STR) * sizeof(float);   // 67584 B
    cudaFuncSetAttribute(cls_k, cudaFuncAttributeMaxDynamicSharedMemorySize, cls_smem);
    cudaFuncSetAttribute(enc_mma_k, cudaFuncAttributeMaxDynamicSharedMemorySize, enc_smem);

    const int nblk = (N_EDGES + 63) / 64;
    zero_k<<<(N_NODES * HID + 255) / 256, 256>>>();
    prep_all_k<<<(KTOT * HID + 255) / 256, 256>>>(Wc1, W1, W2);
    prep_gru_k<<<(32 * 384 + 255) / 256, 256>>>(Wih, Whh);
    enc_mma_k<<<nblk, 128, enc_smem>>>(ea, eidx, b1, g1, be1, b2, g2, be2);
    gru_k<<<N_NODES / 8, 384>>>(hprev, bih, bhh);
    cls_k<<<nblk, 128, cls_smem>>>(ea, eidx, bc1, Wc2, bc2, out);
}

// round 12
// speedup vs baseline: 1.7229x; 1.0703x over previous
#include <cuda_runtime.h>

#define N_NODES 50000
#define N_EDGES 500000
#define HID 128
#define EDIM 32
#define KTOT (2 * HID + EDIM)   // 288
#define RPAD 292                // cls smem row stride
#define NKS (KTOT / 8)          // 36 k-steps for cls
#define S2STR 132               // enc smem row stride (132 % 32 = 4)

typedef unsigned long long u64;

// ---------------- scratch (device globals: no allocation allowed) ----------------
__device__ float    g_sum [N_NODES * HID];
__device__ float    g_cnt [N_NODES];
__device__ float    g_hnew[N_NODES * HID];
__device__ unsigned g_wtf [KTOT * HID];       // Wc1 tf32
__device__ unsigned g_w1tf[EDIM * HID];       // W1  tf32
__device__ unsigned g_w2tf[HID * HID];        // W2  tf32
__device__ u64      g_wihT4[32 * 384 * 2];    // Wih transposed+interleaved
__device__ u64      g_whhT4[32 * 384 * 2];    // Whh transposed+interleaved

// ---------------- zero scratch ----------------
__global__ void zero_k() {
    int i = blockIdx.x * blockDim.x + threadIdx.x;
    if (i < N_NODES * HID) g_sum[i] = 0.0f;
    if (i < N_NODES)       g_cnt[i] = 0.0f;
}

// ---------------- tf32 helpers ----------------
__device__ __forceinline__ unsigned f2tf(float x) {
    unsigned r;
    asm("cvt.rna.tf32.f32 %0, %1;" : "=r"(r) : "f"(x));
    return r;
}
__device__ __forceinline__ float tf32f(float x) { return __uint_as_float(f2tf(x)); }

__global__ void prep_all_k(const float* __restrict__ Wc1,
                           const float* __restrict__ W1,
                           const float* __restrict__ W2) {
    int i = blockIdx.x * blockDim.x + threadIdx.x;
    if (i < KTOT * HID) g_wtf [i] = f2tf(Wc1[i]);
    if (i < EDIM * HID) g_w1tf[i] = f2tf(W1[i]);
    if (i < HID  * HID) g_w2tf[i] = f2tf(W2[i]);
}

__device__ __forceinline__ u64 pk2(float lo, float hi) {
    return ((u64)__float_as_uint(hi) << 32) | (u64)__float_as_uint(lo);
}

__global__ void prep_gru_k(const float* __restrict__ Wih, const float* __restrict__ Whh) {
    int i = blockIdx.x * blockDim.x + threadIdx.x;
    if (i < 32 * 384) {
        int k4 = i / 384, j = i - k4 * 384;
        const float* wi = Wih + (long)j * HID + k4 * 4;
        const float* wh = Whh + (long)j * HID + k4 * 4;
        g_wihT4[i * 2]     = pk2(wi[0], wi[1]);
        g_wihT4[i * 2 + 1] = pk2(wi[2], wi[3]);
        g_whhT4[i * 2]     = pk2(wh[0], wh[1]);
        g_whhT4[i * 2 + 1] = pk2(wh[2], wh[3]);
    }
}

__device__ __forceinline__ void mma_tf32(float* d,
                                         unsigned a0, unsigned a1, unsigned a2, unsigned a3,
                                         unsigned b0, unsigned b1) {
    asm("mma.sync.aligned.m16n8k8.row.col.f32.tf32.tf32.f32 "
        "{%0,%1,%2,%3}, {%4,%5,%6,%7}, {%8,%9}, {%0,%1,%2,%3};"
        : "+f"(d[0]), "+f"(d[1]), "+f"(d[2]), "+f"(d[3])
        : "r"(a0), "r"(a1), "r"(a2), "r"(a3), "r"(b0), "r"(b1));
}

// ---------------- packed fp32x2 helpers (FFMA2, gru) ----------------
__device__ __forceinline__ u64 fma2(u64 a, u64 b, u64 c) {
    u64 d;
    asm("fma.rn.f32x2 %0, %1, %2, %3;" : "=l"(d) : "l"(a), "l"(b), "l"(c));
    return d;
}
__device__ __forceinline__ void unpack2(u64 v, float& lo, float& hi) {
    asm("mov.b64 {%0, %1}, %2;" : "=f"(lo), "=f"(hi) : "l"(v));
}
__device__ __forceinline__ float4 ldg4(const float* p) { return __ldg((const float4*)p); }

__device__ __forceinline__ float4 ln_relu(float4 v, float4 g, float4 b) {
    float s = v.x + v.y + v.z + v.w;
    float q = v.x * v.x + v.y * v.y + v.z * v.z + v.w * v.w;
#pragma unroll
    for (int o = 16; o > 0; o >>= 1) {
        s += __shfl_xor_sync(0xffffffffu, s, o);
        q += __shfl_xor_sync(0xffffffffu, q, o);
    }
    float mu   = s * (1.0f / 128.0f);
    float var  = q * (1.0f / 128.0f) - mu * mu;
    float rstd = rsqrtf(var + 1e-5f);
    float4 r;
    r.x = fmaxf((v.x - mu) * rstd * g.x + b.x, 0.0f);
    r.y = fmaxf((v.y - mu) * rstd * g.y + b.y, 0.0f);
    r.z = fmaxf((v.z - mu) * rstd * g.z + b.z, 0.0f);
    r.w = fmaxf((v.w - mu) * rstd * g.w + b.w, 0.0f);
    return r;
}

// ---------------- kernel 1: edge encoder via tf32 MMA, single-buffer, reg-LN ------
// block = 128 threads = 4 warps; 64 edges/block. smem ~35 KB static -> 4 blocks/SM.
__global__ void __launch_bounds__(128, 4) enc_mma_k(
    const float* __restrict__ ea, const int* __restrict__ eidx,
    const float* __restrict__ b1, const float* __restrict__ g1,
    const float* __restrict__ be1,
    const float* __restrict__ b2, const float* __restrict__ g2,
    const float* __restrict__ be2)
{
    __shared__ float buf[64 * S2STR];   // 33.8 KB single A/activation buffer
    __shared__ float st1[64 * 2];       // layer-1 LN stats (sum, sumsq)
    __shared__ float st2[64 * 2];       // layer-2 LN stats
    __shared__ int   sidx[64];          // src node per edge row

    const int tid  = threadIdx.x;
    const int w    = tid >> 5;
    const int lane = tid & 31;
    const int l4   = lane >> 2;
    const int lm   = lane & 3;
    const long base = (long)blockIdx.x * 64;
    const int nw   = w * 32;

    // ---- phase A: zero stats, cache eidx, gather edge_attr -> buf (tf32) ----
    if (tid < 64) {
        st1[tid * 2] = 0.f; st1[tid * 2 + 1] = 0.f;
        st2[tid * 2] = 0.f; st2[tid * 2 + 1] = 0.f;
        long eg = base + tid;
        sidx[tid] = (eg < N_EDGES) ? eidx[eg] : -1;
    }
    for (int idx = tid; idx < 64 * 8; idx += 128) {
        int e = idx >> 3, q = idx & 7;
        long eg = base + e;
        float4 v = make_float4(0.f, 0.f, 0.f, 0.f);
        if (eg < N_EDGES) v = ldg4(ea + eg * EDIM + q * 4);
        float4 t = make_float4(tf32f(v.x), tf32f(v.y), tf32f(v.z), tf32f(v.w));
        *(float4*)&buf[e * S2STR + q * 4] = t;
    }
    __syncthreads();

    float acc[4][4][4];

    // ---- phase B: layer-1 MMA (K=32, 4 k-steps) ----
#pragma unroll
    for (int mt = 0; mt < 4; ++mt)
#pragma unroll
        for (int nt = 0; nt < 4; ++nt)
#pragma unroll
            for (int i = 0; i < 4; ++i) acc[mt][nt][i] = 0.0f;

#pragma unroll
    for (int ks = 0; ks < 4; ++ks) {
        const int k0 = ks * 8;
        unsigned a[4][4];
#pragma unroll
        for (int mt = 0; mt < 4; ++mt) {
            const float* rp = buf + (mt * 16 + l4) * S2STR + k0 + lm;
            a[mt][0] = __float_as_uint(rp[0]);
            a[mt][1] = __float_as_uint(rp[8 * S2STR]);
            a[mt][2] = __float_as_uint(rp[4]);
            a[mt][3] = __float_as_uint(rp[8 * S2STR + 4]);
        }
#pragma unroll
        for (int nt = 0; nt < 4; ++nt) {
            int n = nw + nt * 8 + l4;
            unsigned bb0 = __ldg(g_w1tf + (k0 + lm) * HID + n);
            unsigned bb1 = __ldg(g_w1tf + (k0 + lm + 4) * HID + n);
#pragma unroll
            for (int mt = 0; mt < 4; ++mt)
                mma_tf32(acc[mt][nt], a[mt][0], a[mt][1], a[mt][2], a[mt][3], bb0, bb1);
        }
    }
    __syncthreads();   // all buf reads done before LN writes

    // ---- phase C: layer-1 bias + LN stats (registers + quad shfl + smem atomics) --
    {
        float bv0[4], bv1[4];
#pragma unroll
        for (int nt = 0; nt < 4; ++nt) {
            int c = nw + nt * 8 + lm * 2;
            bv0[nt] = __ldg(b1 + c); bv1[nt] = __ldg(b1 + c + 1);
        }
#pragma unroll
        for (int mt = 0; mt < 4; ++mt) {
            float s0 = 0.f, q0 = 0.f, s1 = 0.f, q1 = 0.f;
#pragma unroll
            for (int nt = 0; nt < 4; ++nt) {
                acc[mt][nt][0] += bv0[nt]; acc[mt][nt][1] += bv1[nt];
                acc[mt][nt][2] += bv0[nt]; acc[mt][nt][3] += bv1[nt];
                s0 += acc[mt][nt][0] + acc[mt][nt][1];
                q0 += acc[mt][nt][0] * acc[mt][nt][0] + acc[mt][nt][1] * acc[mt][nt][1];
                s1 += acc[mt][nt][2] + acc[mt][nt][3];
                q1 += acc[mt][nt][2] * acc[mt][nt][2] + acc[mt][nt][3] * acc[mt][nt][3];
            }
            s0 += __shfl_xor_sync(0xffffffffu, s0, 1); s0 += __shfl_xor_sync(0xffffffffu, s0, 2);
            q0 += __shfl_xor_sync(0xffffffffu, q0, 1); q0 += __shfl_xor_sync(0xffffffffu, q0, 2);
            s1 += __shfl_xor_sync(0xffffffffu, s1, 1); s1 += __shfl_xor_sync(0xffffffffu, s1, 2);
            q1 += __shfl_xor_sync(0xffffffffu, q1, 1); q1 += __shfl_xor_sync(0xffffffffu, q1, 2);
            if (lm == 0) {
                int r0 = mt * 16 + l4;
                atomicAdd(&st1[r0 * 2],  s0); atomicAdd(&st1[r0 * 2 + 1],  q0);
                atomicAdd(&st1[(r0 + 8) * 2], s1); atomicAdd(&st1[(r0 + 8) * 2 + 1], q1);
            }
        }
    }
    __syncthreads();

    // normalize + affine + relu + tf32 -> buf (full 128-wide rows)
    {
        float gv0[4], gv1[4], ev0[4], ev1[4];
#pragma unroll
        for (int nt = 0; nt < 4; ++nt) {
            int c = nw + nt * 8 + lm * 2;
            gv0[nt] = __ldg(g1 + c);  gv1[nt] = __ldg(g1 + c + 1);
            ev0[nt] = __ldg(be1 + c); ev1[nt] = __ldg(be1 + c + 1);
        }
#pragma unroll
        for (int mt = 0; mt < 4; ++mt) {
            int r0 = mt * 16 + l4, r1 = r0 + 8;
            float mu0 = st1[r0 * 2] * (1.0f / 128.0f);
            float va0 = st1[r0 * 2 + 1] * (1.0f / 128.0f) - mu0 * mu0;
            float rs0 = rsqrtf(va0 + 1e-5f);
            float mu1 = st1[r1 * 2] * (1.0f / 128.0f);
            float va1 = st1[r1 * 2 + 1] * (1.0f / 128.0f) - mu1 * mu1;
            float rs1 = rsqrtf(va1 + 1e-5f);
#pragma unroll
            for (int nt = 0; nt < 4; ++nt) {
                int c = nw + nt * 8 + lm * 2;
                buf[r0 * S2STR + c]     = tf32f(fmaxf((acc[mt][nt][0] - mu0) * rs0 * gv0[nt] + ev0[nt], 0.f));
                buf[r0 * S2STR + c + 1] = tf32f(fmaxf((acc[mt][nt][1] - mu0) * rs0 * gv1[nt] + ev1[nt], 0.f));
                buf[r1 * S2STR + c]     = tf32f(fmaxf((acc[mt][nt][2] - mu1) * rs1 * gv0[nt] + ev0[nt], 0.f));
                buf[r1 * S2STR + c + 1] = tf32f(fmaxf((acc[mt][nt][3] - mu1) * rs1 * gv1[nt] + ev1[nt], 0.f));
            }
        }
    }
    __syncthreads();

    // ---- phase D: layer-2 MMA (K=128, 16 k-steps) ----
#pragma unroll
    for (int mt = 0; mt < 4; ++mt)
#pragma unroll
        for (int nt = 0; nt < 4; ++nt)
#pragma unroll
            for (int i = 0; i < 4; ++i) acc[mt][nt][i] = 0.0f;

#pragma unroll 4
    for (int ks = 0; ks < 16; ++ks) {
        const int k0 = ks * 8;
        unsigned a[4][4];
#pragma unroll
        for (int mt = 0; mt < 4; ++mt) {
            const float* rp = buf + (mt * 16 + l4) * S2STR + k0 + lm;
            a[mt][0] = __float_as_uint(rp[0]);
            a[mt][1] = __float_as_uint(rp[8 * S2STR]);
            a[mt][2] = __float_as_uint(rp[4]);
            a[mt][3] = __float_as_uint(rp[8 * S2STR + 4]);
        }
#pragma unroll
        for (int nt = 0; nt < 4; ++nt) {
            int n = nw + nt * 8 + l4;
            unsigned bb0 = __ldg(g_w2tf + (k0 + lm) * HID + n);
            unsigned bb1 = __ldg(g_w2tf + (k0 + lm + 4) * HID + n);
#pragma unroll
            for (int mt = 0; mt < 4; ++mt)
                mma_tf32(acc[mt][nt], a[mt][0], a[mt][1], a[mt][2], a[mt][3], bb0, bb1);
        }
    }

    // ---- phase E: layer-2 bias + LN stats ----
    {
        float bv0[4], bv1[4];
#pragma unroll
        for (int nt = 0; nt < 4; ++nt) {
            int c = nw + nt * 8 + lm * 2;
            bv0[nt] = __ldg(b2 + c); bv1[nt] = __ldg(b2 + c + 1);
        }
#pragma unroll
        for (int mt = 0; mt < 4; ++mt) {
            float s0 = 0.f, q0 = 0.f, s1 = 0.f, q1 = 0.f;
#pragma unroll
            for (int nt = 0; nt < 4; ++nt) {
                acc[mt][nt][0] += bv0[nt]; acc[mt][nt][1] += bv1[nt];
                acc[mt][nt][2] += bv0[nt]; acc[mt][nt][3] += bv1[nt];
                s0 += acc[mt][nt][0] + acc[mt][nt][1];
                q0 += acc[mt][nt][0] * acc[mt][nt][0] + acc[mt][nt][1] * acc[mt][nt][1];
                s1 += acc[mt][nt][2] + acc[mt][nt][3];
                q1 += acc[mt][nt][2] * acc[mt][nt][2] + acc[mt][nt][3] * acc[mt][nt][3];
            }
            s0 += __shfl_xor_sync(0xffffffffu, s0, 1); s0 += __shfl_xor_sync(0xffffffffu, s0, 2);
            q0 += __shfl_xor_sync(0xffffffffu, q0, 1); q0 += __shfl_xor_sync(0xffffffffu, q0, 2);
            s1 += __shfl_xor_sync(0xffffffffu, s1, 1); s1 += __shfl_xor_sync(0xffffffffu, s1, 2);
            q1 += __shfl_xor_sync(0xffffffffu, q1, 1); q1 += __shfl_xor_sync(0xffffffffu, q1, 2);
            if (lm == 0) {
                int r0 = mt * 16 + l4;
                atomicAdd(&st2[r0 * 2],  s0); atomicAdd(&st2[r0 * 2 + 1],  q0);
                atomicAdd(&st2[(r0 + 8) * 2], s1); atomicAdd(&st2[(r0 + 8) * 2 + 1], q1);
            }
        }
    }
    __syncthreads();

    // normalize + affine + relu + scatter-add to g_sum
    {
        float gv0[4], gv1[4], ev0[4], ev1[4];
#pragma unroll
        for (int nt = 0; nt < 4; ++nt) {
            int c = nw + nt * 8 + lm * 2;
            gv0[nt] = __ldg(g2 + c);  gv1[nt] = __ldg(g2 + c + 1);
            ev0[nt] = __ldg(be2 + c); ev1[nt] = __ldg(be2 + c + 1);
        }
#pragma unroll
        for (int mt = 0; mt < 4; ++mt) {
            int r0 = mt * 16 + l4, r1 = r0 + 8;
            float mu0 = st2[r0 * 2] * (1.0f / 128.0f);
            float va0 = st2[r0 * 2 + 1] * (1.0f / 128.0f) - mu0 * mu0;
            float rs0 = rsqrtf(va0 + 1e-5f);
            float mu1 = st2[r1 * 2] * (1.0f / 128.0f);
            float va1 = st2[r1 * 2 + 1] * (1.0f / 128.0f) - mu1 * mu1;
            float rs1 = rsqrtf(va1 + 1e-5f);
            int s0i = sidx[r0], s1i = sidx[r1];
#pragma unroll
            for (int nt = 0; nt < 4; ++nt) {
                int c = nw + nt * 8 + lm * 2;
                if (s0i >= 0) {
                    float* dp = g_sum + (long)s0i * HID + c;
                    atomicAdd(dp,     fmaxf((acc[mt][nt][0] - mu0) * rs0 * gv0[nt] + ev0[nt], 0.f));
                    atomicAdd(dp + 1, fmaxf((acc[mt][nt][1] - mu0) * rs0 * gv1[nt] + ev1[nt], 0.f));
                }
                if (s1i >= 0) {
                    float* dp = g_sum + (long)s1i * HID + c;
                    atomicAdd(dp,     fmaxf((acc[mt][nt][2] - mu1) * rs1 * gv0[nt] + ev0[nt], 0.f));
                    atomicAdd(dp + 1, fmaxf((acc[mt][nt][3] - mu1) * rs1 * gv1[nt] + ev1[nt], 0.f));
                }
            }
        }
    }
    if (tid < 64 && sidx[tid] >= 0) atomicAdd(&g_cnt[sidx[tid]], 1.0f);
}

// ---------------- kernel 2: mean + GRUCell (unchanged) ----------
__global__ void __launch_bounds__(384) gru_k(
    const float* __restrict__ hprev,
    const float* __restrict__ bih, const float* __restrict__ bhh)
{
    __shared__ float sA[8][HID];
    __shared__ float sH[8][HID];
    __shared__ float sR[8][HID];
    __shared__ float sZ[8][HID];

    const int tid = threadIdx.x;
    const long node0 = (long)blockIdx.x * 8;

    for (int idx = tid; idx < 8 * HID; idx += 384) {
        int n = idx >> 7, k = idx & 127;
        long g = (node0 + n) * HID + k;
        float c = g_cnt[node0 + n];
        sA[n][k] = g_sum[g] / fmaxf(c, 1.0f);
        sH[n][k] = hprev[g];
    }
    __syncthreads();

    const int j = tid;
    u64 gx2[8], gh2[8];
#pragma unroll
    for (int n = 0; n < 8; ++n) { gx2[n] = 0ull; gh2[n] = 0ull; }

    const ulonglong2* wiT = (const ulonglong2*)g_wihT4;
    const ulonglong2* whT = (const ulonglong2*)g_whhT4;
#pragma unroll 4
    for (int k4 = 0; k4 < HID / 4; ++k4) {
        ulonglong2 wi2 = __ldg(wiT + k4 * 384 + j);
        ulonglong2 wh2 = __ldg(whT + k4 * 384 + j);
#pragma unroll
        for (int n = 0; n < 8; ++n) {
            ulonglong2 a2 = *(const ulonglong2*)&sA[n][k4 * 4];
            ulonglong2 h2 = *(const ulonglong2*)&sH[n][k4 * 4];
            gx2[n] = fma2(a2.x, wi2.x, gx2[n]);
            gx2[n] = fma2(a2.y, wi2.y, gx2[n]);
            gh2[n] = fma2(h2.x, wh2.x, gh2[n]);
            gh2[n] = fma2(h2.y, wh2.y, gh2[n]);
        }
    }

    float gx[8], gh[8];
    const float bi = __ldg(bih + j), bh = __ldg(bhh + j);
#pragma unroll
    for (int n = 0; n < 8; ++n) {
        float lo, hi;
        unpack2(gx2[n], lo, hi); gx[n] = bi + lo + hi;
        unpack2(gh2[n], lo, hi); gh[n] = bh + lo + hi;
    }

    if (j < HID) {
#pragma unroll
        for (int n = 0; n < 8; ++n)
            sR[n][j] = 1.0f / (1.0f + expf(-(gx[n] + gh[n])));
    } else if (j < 2 * HID) {
        int jj = j - HID;
#pragma unroll
        for (int n = 0; n < 8; ++n)
            sZ[n][jj] = 1.0f / (1.0f + expf(-(gx[n] + gh[n])));
    }
    __syncthreads();
    if (j >= 2 * HID) {
        int jj = j - 2 * HID;
#pragma unroll
        for (int n = 0; n < 8; ++n) {
            float r  = sR[n][jj];
            float nn = tanhf(gx[n] + r * gh[n]);
            float z  = sZ[n][jj];
            g_hnew[(node0 + n) * HID + jj] = (1.0f - z) * nn + z * sH[n][jj];
        }
    }
}

// ---------------- kernel 3: classifier via tf32 mma.sync (unchanged) ----------------
__global__ void __launch_bounds__(128) cls_k(
    const float* __restrict__ ea, const int* __restrict__ eidx,
    const float* __restrict__ bc1, const float* __restrict__ Wc2,
    const float* __restrict__ bc2, float* __restrict__ out)
{
    extern __shared__ float sm[];
    float* srep = sm;
    float* part = sm + 64 * RPAD;

    const int tid  = threadIdx.x;
    const int w    = tid >> 5;
    const int lane = tid & 31;
    const int l4   = lane >> 2;
    const int lm   = lane & 3;
    const long base = (long)blockIdx.x * 64;

    if (tid < 64) part[tid] = 0.0f;

    for (int idx = tid; idx < 64 * 72; idx += 128) {
        int e = idx / 72, q = idx - e * 72;
        long eg = base + e;
        float4 v = make_float4(0.f, 0.f, 0.f, 0.f);
        if (eg < N_EDGES) {
            if (q < 32) {
                int s = eidx[eg];
                v = *(const float4*)(g_hnew + (long)s * HID + q * 4);
            } else if (q < 64) {
                int d = eidx[N_EDGES + eg];
                v = *(const float4*)(g_hnew + (long)d * HID + (q - 32) * 4);
            } else {
                v = *(const float4*)(ea + eg * EDIM + (q - 64) * 4);
            }
        }
        float4 t = make_float4(tf32f(v.x), tf32f(v.y), tf32f(v.z), tf32f(v.w));
        *(float4*)&srep[e * RPAD + q * 4] = t;
    }
    __syncthreads();

    float acc[4][4][4];
#pragma unroll
    for (int mt = 0; mt < 4; ++mt)
#pragma unroll
        for (int nt = 0; nt < 4; ++nt)
#pragma unroll
            for (int i = 0; i < 4; ++i) acc[mt][nt][i] = 0.0f;

    const int nw = w * 32;
#pragma unroll 4
    for (int ks = 0; ks < NKS; ++ks) {
        const int k0 = ks * 8;
        unsigned a[4][4];
#pragma unroll
        for (int mt = 0; mt < 4; ++mt) {
            const float* rp = srep + (mt * 16 + l4) * RPAD + k0 + lm;
            a[mt][0] = __float_as_uint(rp[0]);
            a[mt][1] = __float_as_uint(rp[8 * RPAD]);
            a[mt][2] = __float_as_uint(rp[4]);
            a[mt][3] = __float_as_uint(rp[8 * RPAD + 4]);
        }
#pragma unroll
        for (int nt = 0; nt < 4; ++nt) {
            int n = nw + nt * 8 + l4;
            unsigned b0 = __ldg(g_wtf + (k0 + lm) * HID + n);
            unsigned b1 = __ldg(g_wtf + (k0 + lm + 4) * HID + n);
#pragma unroll
            for (int mt = 0; mt < 4; ++mt)
                mma_tf32(acc[mt][nt], a[mt][0], a[mt][1], a[mt][2], a[mt][3], b0, b1);
        }
    }

#pragma unroll
    for (int nt = 0; nt < 4; ++nt) {
        int n0 = nw + nt * 8 + lm * 2;
        float bcA = __ldg(bc1 + n0),  bcB = __ldg(bc1 + n0 + 1);
        float w2A = __ldg(Wc2 + n0),  w2B = __ldg(Wc2 + n0 + 1);
#pragma unroll
        for (int mt = 0; mt < 4; ++mt) {
            float vlo = fmaxf(acc[mt][nt][0] + bcA, 0.f) * w2A
                      + fmaxf(acc[mt][nt][1] + bcB, 0.f) * w2B;
            float vhi = fmaxf(acc[mt][nt][2] + bcA, 0.f) * w2A
                      + fmaxf(acc[mt][nt][3] + bcB, 0.f) * w2B;
            vlo += __shfl_xor_sync(0xffffffffu, vlo, 1);
            vlo += __shfl_xor_sync(0xffffffffu, vlo, 2);
            vhi += __shfl_xor_sync(0xffffffffu, vhi, 1);
            vhi += __shfl_xor_sync(0xffffffffu, vhi, 2);
            if (lm == 0) {
                atomicAdd(&part[mt * 16 + l4],     vlo);
                atomicAdd(&part[mt * 16 + l4 + 8], vhi);
            }
        }
    }
    __syncthreads();

    if (tid < 64) {
        long eg = base + tid;
        if (eg < N_EDGES) out[eg] = part[tid] + __ldg(bc2);
    }
}

// ---------------- launch ----------------
extern "C" void kernel_launch(void* const* d_in, const int* in_sizes, int n_in,
                              void* d_out, int out_size)
{
    (void)in_sizes; (void)n_in; (void)out_size;
    const int*   eidx  = (const int*)  d_in[1];
    const float* ea    = (const float*)d_in[2];
    const float* hprev = (const float*)d_in[3];
    const float* W1 = (const float*)d_in[4];
    const float* b1 = (const float*)d_in[5];
    const float* g1 = (const float*)d_in[6];
    const float* be1= (const float*)d_in[7];
    const float* W2 = (const float*)d_in[8];
    const float* b2 = (const float*)d_in[9];
    const float* g2 = (const float*)d_in[10];
    const float* be2= (const float*)d_in[11];
    const float* Wih= (const float*)d_in[12];
    const float* bih= (const float*)d_in[13];
    const float* Whh= (const float*)d_in[14];
    const float* bhh= (const float*)d_in[15];
    const float* Wc1= (const float*)d_in[16];
    const float* bc1= (const float*)d_in[17];
    const float* Wc2= (const float*)d_in[18];
    const float* bc2= (const float*)d_in[19];
    float* out = (float*)d_out;

    const int cls_smem = (64 * RPAD + 64) * sizeof(float);   // 75008 B
    cudaFuncSetAttribute(cls_k, cudaFuncAttributeMaxDynamicSharedMemorySize, cls_smem);

    const int nblk = (N_EDGES + 63) / 64;
    zero_k<<<(N_NODES * HID + 255) / 256, 256>>>();
    prep_all_k<<<(KTOT * HID + 255) / 256, 256>>>(Wc1, W1, W2);
    prep_gru_k<<<(32 * 384 + 255) / 256, 256>>>(Wih, Whh);
    enc_mma_k<<<nblk, 128>>>(ea, eidx, b1, g1, be1, b2, g2, be2);
    gru_k<<<N_NODES / 8, 384>>>(hprev, bih, bhh);
    cls_k<<<nblk, 128, cls_smem>>>(ea, eidx, bc1, Wc2, bc2, out);
}

// round 13
// speedup vs baseline: 1.7671x; 1.0256x over previous
#include <cuda_runtime.h>

#define N_NODES 50000
#define N_EDGES 500000
#define HID 128
#define EDIM 32
#define KTOT (2 * HID + EDIM)   // 288
#define S2STR 132               // enc smem row stride (132 % 32 = 4)
#define CSTR 164                // cls smem row stride (164 % 32 = 4)

typedef unsigned long long u64;

// ---------------- scratch (device globals: no allocation allowed) ----------------
__device__ float    g_sum [N_NODES * HID];
__device__ float    g_cnt [N_NODES];
__device__ float    g_hnew[N_NODES * HID];
__device__ unsigned g_wtf [KTOT * HID];       // Wc1 tf32
__device__ unsigned g_w1tf[EDIM * HID];       // W1  tf32
__device__ unsigned g_w2tf[HID * HID];        // W2  tf32
__device__ u64      g_wihT4[32 * 384 * 2];    // Wih transposed+interleaved
__device__ u64      g_whhT4[32 * 384 * 2];    // Whh transposed+interleaved

// ---------------- zero scratch ----------------
__global__ void zero_k() {
    int i = blockIdx.x * blockDim.x + threadIdx.x;
    if (i < N_NODES * HID) g_sum[i] = 0.0f;
    if (i < N_NODES)       g_cnt[i] = 0.0f;
}

// ---------------- tf32 helpers ----------------
__device__ __forceinline__ unsigned f2tf(float x) {
    unsigned r;
    asm("cvt.rna.tf32.f32 %0, %1;" : "=r"(r) : "f"(x));
    return r;
}
__device__ __forceinline__ float tf32f(float x) { return __uint_as_float(f2tf(x)); }

__global__ void prep_all_k(const float* __restrict__ Wc1,
                           const float* __restrict__ W1,
                           const float* __restrict__ W2) {
    int i = blockIdx.x * blockDim.x + threadIdx.x;
    if (i < KTOT * HID) g_wtf [i] = f2tf(Wc1[i]);
    if (i < EDIM * HID) g_w1tf[i] = f2tf(W1[i]);
    if (i < HID  * HID) g_w2tf[i] = f2tf(W2[i]);
}

__device__ __forceinline__ u64 pk2(float lo, float hi) {
    return ((u64)__float_as_uint(hi) << 32) | (u64)__float_as_uint(lo);
}

__global__ void prep_gru_k(const float* __restrict__ Wih, const float* __restrict__ Whh) {
    int i = blockIdx.x * blockDim.x + threadIdx.x;
    if (i < 32 * 384) {
        int k4 = i / 384, j = i - k4 * 384;
        const float* wi = Wih + (long)j * HID + k4 * 4;
        const float* wh = Whh + (long)j * HID + k4 * 4;
        g_wihT4[i * 2]     = pk2(wi[0], wi[1]);
        g_wihT4[i * 2 + 1] = pk2(wi[2], wi[3]);
        g_whhT4[i * 2]     = pk2(wh[0], wh[1]);
        g_whhT4[i * 2 + 1] = pk2(wh[2], wh[3]);
    }
}

__device__ __forceinline__ void mma_tf32(float* d,
                                         unsigned a0, unsigned a1, unsigned a2, unsigned a3,
                                         unsigned b0, unsigned b1) {
    asm("mma.sync.aligned.m16n8k8.row.col.f32.tf32.tf32.f32 "
        "{%0,%1,%2,%3}, {%4,%5,%6,%7}, {%8,%9}, {%0,%1,%2,%3};"
        : "+f"(d[0]), "+f"(d[1]), "+f"(d[2]), "+f"(d[3])
        : "r"(a0), "r"(a1), "r"(a2), "r"(a3), "r"(b0), "r"(b1));
}

// ---------------- packed fp32x2 helpers (FFMA2, gru) ----------------
__device__ __forceinline__ u64 fma2(u64 a, u64 b, u64 c) {
    u64 d;
    asm("fma.rn.f32x2 %0, %1, %2, %3;" : "=l"(d) : "l"(a), "l"(b), "l"(c));
    return d;
}
__device__ __forceinline__ void unpack2(u64 v, float& lo, float& hi) {
    asm("mov.b64 {%0, %1}, %2;" : "=f"(lo), "=f"(hi) : "l"(v));
}
__device__ __forceinline__ float4 ldg4(const float* p) { return __ldg((const float4*)p); }

// ---------------- kernel 1: edge encoder via tf32 MMA, single-buffer, reg-LN ------
__global__ void __launch_bounds__(128, 4) enc_mma_k(
    const float* __restrict__ ea, const int* __restrict__ eidx,
    const float* __restrict__ b1, const float* __restrict__ g1,
    const float* __restrict__ be1,
    const float* __restrict__ b2, const float* __restrict__ g2,
    const float* __restrict__ be2)
{
    __shared__ float buf[64 * S2STR];
    __shared__ float st1[64 * 2];
    __shared__ float st2[64 * 2];
    __shared__ int   sidx[64];

    const int tid  = threadIdx.x;
    const int w    = tid >> 5;
    const int lane = tid & 31;
    const int l4   = lane >> 2;
    const int lm   = lane & 3;
    const long base = (long)blockIdx.x * 64;
    const int nw   = w * 32;

    if (tid < 64) {
        st1[tid * 2] = 0.f; st1[tid * 2 + 1] = 0.f;
        st2[tid * 2] = 0.f; st2[tid * 2 + 1] = 0.f;
        long eg = base + tid;
        sidx[tid] = (eg < N_EDGES) ? eidx[eg] : -1;
    }
    for (int idx = tid; idx < 64 * 8; idx += 128) {
        int e = idx >> 3, q = idx & 7;
        long eg = base + e;
        float4 v = make_float4(0.f, 0.f, 0.f, 0.f);
        if (eg < N_EDGES) v = ldg4(ea + eg * EDIM + q * 4);
        float4 t = make_float4(tf32f(v.x), tf32f(v.y), tf32f(v.z), tf32f(v.w));
        *(float4*)&buf[e * S2STR + q * 4] = t;
    }
    __syncthreads();

    float acc[4][4][4];

#pragma unroll
    for (int mt = 0; mt < 4; ++mt)
#pragma unroll
        for (int nt = 0; nt < 4; ++nt)
#pragma unroll
            for (int i = 0; i < 4; ++i) acc[mt][nt][i] = 0.0f;

#pragma unroll
    for (int ks = 0; ks < 4; ++ks) {
        const int k0 = ks * 8;
        unsigned a[4][4];
#pragma unroll
        for (int mt = 0; mt < 4; ++mt) {
            const float* rp = buf + (mt * 16 + l4) * S2STR + k0 + lm;
            a[mt][0] = __float_as_uint(rp[0]);
            a[mt][1] = __float_as_uint(rp[8 * S2STR]);
            a[mt][2] = __float_as_uint(rp[4]);
            a[mt][3] = __float_as_uint(rp[8 * S2STR + 4]);
        }
#pragma unroll
        for (int nt = 0; nt < 4; ++nt) {
            int n = nw + nt * 8 + l4;
            unsigned bb0 = __ldg(g_w1tf + (k0 + lm) * HID + n);
            unsigned bb1 = __ldg(g_w1tf + (k0 + lm + 4) * HID + n);
#pragma unroll
            for (int mt = 0; mt < 4; ++mt)
                mma_tf32(acc[mt][nt], a[mt][0], a[mt][1], a[mt][2], a[mt][3], bb0, bb1);
        }
    }
    __syncthreads();

    {
        float bv0[4], bv1[4];
#pragma unroll
        for (int nt = 0; nt < 4; ++nt) {
            int c = nw + nt * 8 + lm * 2;
            bv0[nt] = __ldg(b1 + c); bv1[nt] = __ldg(b1 + c + 1);
        }
#pragma unroll
        for (int mt = 0; mt < 4; ++mt) {
            float s0 = 0.f, q0 = 0.f, s1 = 0.f, q1 = 0.f;
#pragma unroll
            for (int nt = 0; nt < 4; ++nt) {
                acc[mt][nt][0] += bv0[nt]; acc[mt][nt][1] += bv1[nt];
                acc[mt][nt][2] += bv0[nt]; acc[mt][nt][3] += bv1[nt];
                s0 += acc[mt][nt][0] + acc[mt][nt][1];
                q0 += acc[mt][nt][0] * acc[mt][nt][0] + acc[mt][nt][1] * acc[mt][nt][1];
                s1 += acc[mt][nt][2] + acc[mt][nt][3];
                q1 += acc[mt][nt][2] * acc[mt][nt][2] + acc[mt][nt][3] * acc[mt][nt][3];
            }
            s0 += __shfl_xor_sync(0xffffffffu, s0, 1); s0 += __shfl_xor_sync(0xffffffffu, s0, 2);
            q0 += __shfl_xor_sync(0xffffffffu, q0, 1); q0 += __shfl_xor_sync(0xffffffffu, q0, 2);
            s1 += __shfl_xor_sync(0xffffffffu, s1, 1); s1 += __shfl_xor_sync(0xffffffffu, s1, 2);
            q1 += __shfl_xor_sync(0xffffffffu, q1, 1); q1 += __shfl_xor_sync(0xffffffffu, q1, 2);
            if (lm == 0) {
                int r0 = mt * 16 + l4;
                atomicAdd(&st1[r0 * 2],  s0); atomicAdd(&st1[r0 * 2 + 1],  q0);
                atomicAdd(&st1[(r0 + 8) * 2], s1); atomicAdd(&st1[(r0 + 8) * 2 + 1], q1);
            }
        }
    }
    __syncthreads();

    {
        float gv0[4], gv1[4], ev0[4], ev1[4];
#pragma unroll
        for (int nt = 0; nt < 4; ++nt) {
            int c = nw + nt * 8 + lm * 2;
            gv0[nt] = __ldg(g1 + c);  gv1[nt] = __ldg(g1 + c + 1);
            ev0[nt] = __ldg(be1 + c); ev1[nt] = __ldg(be1 + c + 1);
        }
#pragma unroll
        for (int mt = 0; mt < 4; ++mt) {
            int r0 = mt * 16 + l4, r1 = r0 + 8;
            float mu0 = st1[r0 * 2] * (1.0f / 128.0f);
            float va0 = st1[r0 * 2 + 1] * (1.0f / 128.0f) - mu0 * mu0;
            float rs0 = rsqrtf(va0 + 1e-5f);
            float mu1 = st1[r1 * 2] * (1.0f / 128.0f);
            float va1 = st1[r1 * 2 + 1] * (1.0f / 128.0f) - mu1 * mu1;
            float rs1 = rsqrtf(va1 + 1e-5f);
#pragma unroll
            for (int nt = 0; nt < 4; ++nt) {
                int c = nw + nt * 8 + lm * 2;
                buf[r0 * S2STR + c]     = tf32f(fmaxf((acc[mt][nt][0] - mu0) * rs0 * gv0[nt] + ev0[nt], 0.f));
                buf[r0 * S2STR + c + 1] = tf32f(fmaxf((acc[mt][nt][1] - mu0) * rs0 * gv1[nt] + ev1[nt], 0.f));
                buf[r1 * S2STR + c]     = tf32f(fmaxf((acc[mt][nt][2] - mu1) * rs1 * gv0[nt] + ev0[nt], 0.f));
                buf[r1 * S2STR + c + 1] = tf32f(fmaxf((acc[mt][nt][3] - mu1) * rs1 * gv1[nt] + ev1[nt], 0.f));
            }
        }
    }
    __syncthreads();

#pragma unroll
    for (int mt = 0; mt < 4; ++mt)
#pragma unroll
        for (int nt = 0; nt < 4; ++nt)
#pragma unroll
            for (int i = 0; i < 4; ++i) acc[mt][nt][i] = 0.0f;

#pragma unroll 4
    for (int ks = 0; ks < 16; ++ks) {
        const int k0 = ks * 8;
        unsigned a[4][4];
#pragma unroll
        for (int mt = 0; mt < 4; ++mt) {
            const float* rp = buf + (mt * 16 + l4) * S2STR + k0 + lm;
            a[mt][0] = __float_as_uint(rp[0]);
            a[mt][1] = __float_as_uint(rp[8 * S2STR]);
            a[mt][2] = __float_as_uint(rp[4]);
            a[mt][3] = __float_as_uint(rp[8 * S2STR + 4]);
        }
#pragma unroll
        for (int nt = 0; nt < 4; ++nt) {
            int n = nw + nt * 8 + l4;
            unsigned bb0 = __ldg(g_w2tf + (k0 + lm) * HID + n);
            unsigned bb1 = __ldg(g_w2tf + (k0 + lm + 4) * HID + n);
#pragma unroll
            for (int mt = 0; mt < 4; ++mt)
                mma_tf32(acc[mt][nt], a[mt][0], a[mt][1], a[mt][2], a[mt][3], bb0, bb1);
        }
    }

    {
        float bv0[4], bv1[4];
#pragma unroll
        for (int nt = 0; nt < 4; ++nt) {
            int c = nw + nt * 8 + lm * 2;
            bv0[nt] = __ldg(b2 + c); bv1[nt] = __ldg(b2 + c + 1);
        }
#pragma unroll
        for (int mt = 0; mt < 4; ++mt) {
            float s0 = 0.f, q0 = 0.f, s1 = 0.f, q1 = 0.f;
#pragma unroll
            for (int nt = 0; nt < 4; ++nt) {
                acc[mt][nt][0] += bv0[nt]; acc[mt][nt][1] += bv1[nt];
                acc[mt][nt][2] += bv0[nt]; acc[mt][nt][3] += bv1[nt];
                s0 += acc[mt][nt][0] + acc[mt][nt][1];
                q0 += acc[mt][nt][0] * acc[mt][nt][0] + acc[mt][nt][1] * acc[mt][nt][1];
                s1 += acc[mt][nt][2] + acc[mt][nt][3];
                q1 += acc[mt][nt][2] * acc[mt][nt][2] + acc[mt][nt][3] * acc[mt][nt][3];
            }
            s0 += __shfl_xor_sync(0xffffffffu, s0, 1); s0 += __shfl_xor_sync(0xffffffffu, s0, 2);
            q0 += __shfl_xor_sync(0xffffffffu, q0, 1); q0 += __shfl_xor_sync(0xffffffffu, q0, 2);
            s1 += __shfl_xor_sync(0xffffffffu, s1, 1); s1 += __shfl_xor_sync(0xffffffffu, s1, 2);
            q1 += __shfl_xor_sync(0xffffffffu, q1, 1); q1 += __shfl_xor_sync(0xffffffffu, q1, 2);
            if (lm == 0) {
                int r0 = mt * 16 + l4;
                atomicAdd(&st2[r0 * 2],  s0); atomicAdd(&st2[r0 * 2 + 1],  q0);
                atomicAdd(&st2[(r0 + 8) * 2], s1); atomicAdd(&st2[(r0 + 8) * 2 + 1], q1);
            }
        }
    }
    __syncthreads();

    {
        float gv0[4], gv1[4], ev0[4], ev1[4];
#pragma unroll
        for (int nt = 0; nt < 4; ++nt) {
            int c = nw + nt * 8 + lm * 2;
            gv0[nt] = __ldg(g2 + c);  gv1[nt] = __ldg(g2 + c + 1);
            ev0[nt] = __ldg(be2 + c); ev1[nt] = __ldg(be2 + c + 1);
        }
#pragma unroll
        for (int mt = 0; mt < 4; ++mt) {
            int r0 = mt * 16 + l4, r1 = r0 + 8;
            float mu0 = st2[r0 * 2] * (1.0f / 128.0f);
            float va0 = st2[r0 * 2 + 1] * (1.0f / 128.0f) - mu0 * mu0;
            float rs0 = rsqrtf(va0 + 1e-5f);
            float mu1 = st2[r1 * 2] * (1.0f / 128.0f);
            float va1 = st2[r1 * 2 + 1] * (1.0f / 128.0f) - mu1 * mu1;
            float rs1 = rsqrtf(va1 + 1e-5f);
            int s0i = sidx[r0], s1i = sidx[r1];
#pragma unroll
            for (int nt = 0; nt < 4; ++nt) {
                int c = nw + nt * 8 + lm * 2;
                if (s0i >= 0) {
                    float* dp = g_sum + (long)s0i * HID + c;
                    atomicAdd(dp,     fmaxf((acc[mt][nt][0] - mu0) * rs0 * gv0[nt] + ev0[nt], 0.f));
                    atomicAdd(dp + 1, fmaxf((acc[mt][nt][1] - mu0) * rs0 * gv1[nt] + ev1[nt], 0.f));
                }
                if (s1i >= 0) {
                    float* dp = g_sum + (long)s1i * HID + c;
                    atomicAdd(dp,     fmaxf((acc[mt][nt][2] - mu1) * rs1 * gv0[nt] + ev0[nt], 0.f));
                    atomicAdd(dp + 1, fmaxf((acc[mt][nt][3] - mu1) * rs1 * gv1[nt] + ev1[nt], 0.f));
                }
            }
        }
    }
    if (tid < 64 && sidx[tid] >= 0) atomicAdd(&g_cnt[sidx[tid]], 1.0f);
}

// ---------------- kernel 2: mean + GRUCell (unchanged) ----------
__global__ void __launch_bounds__(384) gru_k(
    const float* __restrict__ hprev,
    const float* __restrict__ bih, const float* __restrict__ bhh)
{
    __shared__ float sA[8][HID];
    __shared__ float sH[8][HID];
    __shared__ float sR[8][HID];
    __shared__ float sZ[8][HID];

    const int tid = threadIdx.x;
    const long node0 = (long)blockIdx.x * 8;

    for (int idx = tid; idx < 8 * HID; idx += 384) {
        int n = idx >> 7, k = idx & 127;
        long g = (node0 + n) * HID + k;
        float c = g_cnt[node0 + n];
        sA[n][k] = g_sum[g] / fmaxf(c, 1.0f);
        sH[n][k] = hprev[g];
    }
    __syncthreads();

    const int j = tid;
    u64 gx2[8], gh2[8];
#pragma unroll
    for (int n = 0; n < 8; ++n) { gx2[n] = 0ull; gh2[n] = 0ull; }

    const ulonglong2* wiT = (const ulonglong2*)g_wihT4;
    const ulonglong2* whT = (const ulonglong2*)g_whhT4;
#pragma unroll 4
    for (int k4 = 0; k4 < HID / 4; ++k4) {
        ulonglong2 wi2 = __ldg(wiT + k4 * 384 + j);
        ulonglong2 wh2 = __ldg(whT + k4 * 384 + j);
#pragma unroll
        for (int n = 0; n < 8; ++n) {
            ulonglong2 a2 = *(const ulonglong2*)&sA[n][k4 * 4];
            ulonglong2 h2 = *(const ulonglong2*)&sH[n][k4 * 4];
            gx2[n] = fma2(a2.x, wi2.x, gx2[n]);
            gx2[n] = fma2(a2.y, wi2.y, gx2[n]);
            gh2[n] = fma2(h2.x, wh2.x, gh2[n]);
            gh2[n] = fma2(h2.y, wh2.y, gh2[n]);
        }
    }

    float gx[8], gh[8];
    const float bi = __ldg(bih + j), bh = __ldg(bhh + j);
#pragma unroll
    for (int n = 0; n < 8; ++n) {
        float lo, hi;
        unpack2(gx2[n], lo, hi); gx[n] = bi + lo + hi;
        unpack2(gh2[n], lo, hi); gh[n] = bh + lo + hi;
    }

    if (j < HID) {
#pragma unroll
        for (int n = 0; n < 8; ++n)
            sR[n][j] = 1.0f / (1.0f + expf(-(gx[n] + gh[n])));
    } else if (j < 2 * HID) {
        int jj = j - HID;
#pragma unroll
        for (int n = 0; n < 8; ++n)
            sZ[n][jj] = 1.0f / (1.0f + expf(-(gx[n] + gh[n])));
    }
    __syncthreads();
    if (j >= 2 * HID) {
        int jj = j - 2 * HID;
#pragma unroll
        for (int n = 0; n < 8; ++n) {
            float r  = sR[n][jj];
            float nn = tanhf(gx[n] + r * gh[n]);
            float z  = sZ[n][jj];
            g_hnew[(node0 + n) * HID + jj] = (1.0f - z) * nn + z * sH[n][jj];
        }
    }
}

// ---------------- kernel 3: classifier, split-K tf32 mma (42 KB static smem) ------
// Phase A: stage h_src (K 0..127), 16 k-steps. Phase B: h_dst + ea (K 128..287),
// 20 k-steps. Accumulators persist in registers -> identical FLOP order as before.
__global__ void __launch_bounds__(128, 5) cls_k(
    const float* __restrict__ ea, const int* __restrict__ eidx,
    const float* __restrict__ bc1, const float* __restrict__ Wc2,
    const float* __restrict__ bc2, float* __restrict__ out)
{
    __shared__ float buf[64 * CSTR];   // 42.0 KB
    __shared__ float part[64];

    const int tid  = threadIdx.x;
    const int w    = tid >> 5;
    const int lane = tid & 31;
    const int l4   = lane >> 2;
    const int lm   = lane & 3;
    const long base = (long)blockIdx.x * 64;
    const int nw   = w * 32;

    if (tid < 64) part[tid] = 0.0f;

    float acc[4][4][4];
#pragma unroll
    for (int mt = 0; mt < 4; ++mt)
#pragma unroll
        for (int nt = 0; nt < 4; ++nt)
#pragma unroll
            for (int i = 0; i < 4; ++i) acc[mt][nt][i] = 0.0f;

    // ---- phase A: gather h_src rows (128 cols) ----
    for (int idx = tid; idx < 64 * 32; idx += 128) {
        int e = idx >> 5, q = idx & 31;
        long eg = base + e;
        float4 v = make_float4(0.f, 0.f, 0.f, 0.f);
        if (eg < N_EDGES) {
            int s = eidx[eg];
            v = ldg4(g_hnew + (long)s * HID + q * 4);
        }
        float4 t = make_float4(tf32f(v.x), tf32f(v.y), tf32f(v.z), tf32f(v.w));
        *(float4*)&buf[e * CSTR + q * 4] = t;
    }
    __syncthreads();

#pragma unroll 4
    for (int ks = 0; ks < 16; ++ks) {
        const int k0 = ks * 8;                 // buf col == weight row (phase A)
        unsigned a[4][4];
#pragma unroll
        for (int mt = 0; mt < 4; ++mt) {
            const float* rp = buf + (mt * 16 + l4) * CSTR + k0 + lm;
            a[mt][0] = __float_as_uint(rp[0]);
            a[mt][1] = __float_as_uint(rp[8 * CSTR]);
            a[mt][2] = __float_as_uint(rp[4]);
            a[mt][3] = __float_as_uint(rp[8 * CSTR + 4]);
        }
#pragma unroll
        for (int nt = 0; nt < 4; ++nt) {
            int n = nw + nt * 8 + l4;
            unsigned b0 = __ldg(g_wtf + (k0 + lm) * HID + n);
            unsigned b1 = __ldg(g_wtf + (k0 + lm + 4) * HID + n);
#pragma unroll
            for (int mt = 0; mt < 4; ++mt)
                mma_tf32(acc[mt][nt], a[mt][0], a[mt][1], a[mt][2], a[mt][3], b0, b1);
        }
    }
    __syncthreads();

    // ---- phase B: gather h_dst (cols 0..127) + edge_attr (cols 128..159) ----
    for (int idx = tid; idx < 64 * 40; idx += 128) {
        int e = idx / 40, q = idx - e * 40;
        long eg = base + e;
        float4 v = make_float4(0.f, 0.f, 0.f, 0.f);
        if (eg < N_EDGES) {
            if (q < 32) {
                int d = eidx[N_EDGES + eg];
                v = ldg4(g_hnew + (long)d * HID + q * 4);
            } else {
                v = ldg4(ea + eg * EDIM + (q - 32) * 4);
            }
        }
        float4 t = make_float4(tf32f(v.x), tf32f(v.y), tf32f(v.z), tf32f(v.w));
        *(float4*)&buf[e * CSTR + q * 4] = t;
    }
    __syncthreads();

#pragma unroll 4
    for (int ks = 0; ks < 20; ++ks) {
        const int k0l = ks * 8;                // buf col
        const int k0g = 128 + ks * 8;          // weight row
        unsigned a[4][4];
#pragma unroll
        for (int mt = 0; mt < 4; ++mt) {
            const float* rp = buf + (mt * 16 + l4) * CSTR + k0l + lm;
            a[mt][0] = __float_as_uint(rp[0]);
            a[mt][1] = __float_as_uint(rp[8 * CSTR]);
            a[mt][2] = __float_as_uint(rp[4]);
            a[mt][3] = __float_as_uint(rp[8 * CSTR + 4]);
        }
#pragma unroll
        for (int nt = 0; nt < 4; ++nt) {
            int n = nw + nt * 8 + l4;
            unsigned b0 = __ldg(g_wtf + (k0g + lm) * HID + n);
            unsigned b1 = __ldg(g_wtf + (k0g + lm + 4) * HID + n);
#pragma unroll
            for (int mt = 0; mt < 4; ++mt)
                mma_tf32(acc[mt][nt], a[mt][0], a[mt][1], a[mt][2], a[mt][3], b0, b1);
        }
    }

    // ---- epilogue: bias + ReLU + Wc2 dot + quad reduce + smem atomics ----
#pragma unroll
    for (int nt = 0; nt < 4; ++nt) {
        int n0 = nw + nt * 8 + lm * 2;
        float bcA = __ldg(bc1 + n0),  bcB = __ldg(bc1 + n0 + 1);
        float w2A = __ldg(Wc2 + n0),  w2B = __ldg(Wc2 + n0 + 1);
#pragma unroll
        for (int mt = 0; mt < 4; ++mt) {
            float vlo = fmaxf(acc[mt][nt][0] + bcA, 0.f) * w2A
                      + fmaxf(acc[mt][nt][1] + bcB, 0.f) * w2B;
            float vhi = fmaxf(acc[mt][nt][2] + bcA, 0.f) * w2A
                      + fmaxf(acc[mt][nt][3] + bcB, 0.f) * w2B;
            vlo += __shfl_xor_sync(0xffffffffu, vlo, 1);
            vlo += __shfl_xor_sync(0xffffffffu, vlo, 2);
            vhi += __shfl_xor_sync(0xffffffffu, vhi, 1);
            vhi += __shfl_xor_sync(0xffffffffu, vhi, 2);
            if (lm == 0) {
                atomicAdd(&part[mt * 16 + l4],     vlo);
                atomicAdd(&part[mt * 16 + l4 + 8], vhi);
            }
        }
    }
    __syncthreads();

    if (tid < 64) {
        long eg = base + tid;
        if (eg < N_EDGES) out[eg] = part[tid] + __ldg(bc2);
    }
}

// ---------------- launch ----------------
extern "C" void kernel_launch(void* const* d_in, const int* in_sizes, int n_in,
                              void* d_out, int out_size)
{
    (void)in_sizes; (void)n_in; (void)out_size;
    const int*   eidx  = (const int*)  d_in[1];
    const float* ea    = (const float*)d_in[2];
    const float* hprev = (const float*)d_in[3];
    const float* W1 = (const float*)d_in[4];
    const float* b1 = (const float*)d_in[5];
    const float* g1 = (const float*)d_in[6];
    const float* be1= (const float*)d_in[7];
    const float* W2 = (const float*)d_in[8];
    const float* b2 = (const float*)d_in[9];
    const float* g2 = (const float*)d_in[10];
    const float* be2= (const float*)d_in[11];
    const float* Wih= (const float*)d_in[12];
    const float* bih= (const float*)d_in[13];
    const float* Whh= (const float*)d_in[14];
    const float* bhh= (const float*)d_in[15];
    const float* Wc1= (const float*)d_in[16];
    const float* bc1= (const float*)d_in[17];
    const float* Wc2= (const float*)d_in[18];
    const float* bc2= (const float*)d_in[19];
    float* out = (float*)d_out;

    const int nblk = (N_EDGES + 63) / 64;
    zero_k<<<(N_NODES * HID + 255) / 256, 256>>>();
    prep_all_k<<<(KTOT * HID + 255) / 256, 256>>>(Wc1, W1, W2);
    prep_gru_k<<<(32 * 384 + 255) / 256, 256>>>(Wih, Whh);
    enc_mma_k<<<nblk, 128>>>(ea, eidx, b1, g1, be1, b2, g2, be2);
    gru_k<<<N_NODES / 8, 384>>>(hprev, bih, bhh);
    cls_k<<<nblk, 128>>>(ea, eidx, bc1, Wc2, bc2, out);
}